// round 7
// baseline (speedup 1.0000x reference)
#include <cuda_runtime.h>
#include <math.h>
#include <stdint.h>

#define BN   65536
#define NPB  16384
#define NE   262144
#define EPB  128

__device__ __align__(16) float g_P [(size_t)BN * 128];
__device__ __align__(16) float g_dh[(size_t)BN * 64];
__device__ __align__(16) float g_dx[(size_t)BN * 3];
__device__ __align__(16) float g_Bp[14 * 128 * 40];
__device__ __align__(16) float g_W2p[64 * 72];

__device__ __forceinline__ float silu_f(float v) {
    return v * (1.0f / (1.0f + __expf(-v)));
}
__device__ __forceinline__ uint32_t f2tf32(float f) {
    uint32_t r;
    asm("cvt.rna.tf32.f32 %0, %1;" : "=r"(r) : "f"(f));
    return r;
}
__device__ __forceinline__ void mma_tf32(float* c, const uint32_t* a, const uint32_t* b) {
    asm volatile("mma.sync.aligned.m16n8k8.row.col.f32.tf32.tf32.f32 "
        "{%0,%1,%2,%3}, {%4,%5,%6,%7}, {%8,%9}, {%0,%1,%2,%3};"
        : "+f"(c[0]), "+f"(c[1]), "+f"(c[2]), "+f"(c[3])
        : "r"(a[0]), "r"(a[1]), "r"(a[2]), "r"(a[3]), "r"(b[0]), "r"(b[1]));
}
__device__ __forceinline__ void red_add_v2(float* p, float a, float b) {
    asm volatile("red.global.add.v2.f32 [%0], {%1,%2};"
                 :: "l"(p), "f"(a), "f"(b) : "memory");
}
__device__ __forceinline__ void cp_async16(uint32_t dst, const void* src) {
    asm volatile("cp.async.cg.shared.global [%0], [%1], 16;" :: "r"(dst), "l"(src));
}

__global__ void prep_kernel(const float* __restrict__ pw1,
                            const float* __restrict__ hw1,
                            const float* __restrict__ hw2,
                            const float* __restrict__ pw2)
{
    const int stride = gridDim.x * blockDim.x;
    const int idx0 = blockIdx.x * blockDim.x + threadIdx.x;
    {
        float4 z = make_float4(0.f, 0.f, 0.f, 0.f);
        const size_t n1 = (size_t)BN * 16;
        const size_t n2 = (size_t)BN * 3 / 4;
        const size_t total = n1 + n2;
        for (size_t i = idx0; i < total; i += stride) {
            if (i < n1) ((float4*)g_dh)[i] = z;
            else        ((float4*)g_dx)[i - n1] = z;
        }
    }
    for (int i = idx0; i < 14 * 128 * 40; i += stride) {
        const int w = i % 40, n = (i / 40) & 127, c = i / (40 * 128);
        float v = 0.f;
        if (w < 32) {
            const int g = w >> 3, s = w & 7;
            const int k8 = (s >> 1) + ((s & 1) << 2);
            if (c < 4) {
                const int k = c * 32 + g * 8 + k8;
                v = (n < 64) ? pw1[k * 64 + n] : pw1[(128 + k) * 64 + (n - 64)];
            } else if (c < 10) {
                const int k = (c - 4) * 32 + g * 8 + k8;
                v = hw1[k * 128 + n];
            } else {
                const int k = (c - 10) * 32 + g * 8 + k8;
                v = hw2[k * 128 + n];
            }
            v = __uint_as_float(f2tf32(v));
        }
        g_Bp[i] = v;
    }
    for (int i = idx0; i < 64 * 72; i += stride) {
        const int w = i % 72, n = i / 72;
        float v = 0.f;
        if (w < 64) {
            const int g = w >> 3, s = w & 7;
            const int k = g * 8 + (s >> 1) + ((s & 1) << 2);
            v = __uint_as_float(f2tf32(pw2[k * 64 + n]));
        }
        g_W2p[i] = v;
    }
}

// ============ gemm_p: CTA 128x128, warp 32x64, double-buffered ==============
__global__ __launch_bounds__(256, 2) void gemm_p(const float* __restrict__ A)
{
    extern __shared__ float sm[];
    const int BUFW = 10240;
    const int tid  = threadIdx.x;
    const int lane = tid & 31, warp = tid >> 5;
    const int wm = warp & 3, wn = warp >> 2;
    const int gq = lane >> 2, tq = lane & 3;
    const int m0 = blockIdx.x * 128;
    const uint32_t smem_u32 = (uint32_t)__cvta_generic_to_shared(sm);

    float acc[2][8][4];
#pragma unroll
    for (int i = 0; i < 2; i++)
#pragma unroll
        for (int j = 0; j < 8; j++)
#pragma unroll
            for (int q = 0; q < 4; q++) acc[i][j][q] = 0.f;

    float4 ra[4];
    const int am = tid >> 1;
    const int ah = (tid & 1) * 16;

    auto ldgA = [&](int k0) {
        const float* src = A + (size_t)(m0 + am) * 128 + k0 + ah;
        ra[0] = *(const float4*)(src);
        ra[1] = *(const float4*)(src + 4);
        ra[2] = *(const float4*)(src + 8);
        ra[3] = *(const float4*)(src + 12);
    };
    auto stsA = [&](int p) {
        float* bA = sm + p * BUFW;
#pragma unroll
        for (int pg = 0; pg < 2; pg++) {
            const float4 u = ra[pg * 2], v = ra[pg * 2 + 1];
            uint4 w0, w1;
            w0.x = f2tf32(u.x); w0.y = f2tf32(v.x); w0.z = f2tf32(u.y); w0.w = f2tf32(v.y);
            w1.x = f2tf32(u.z); w1.y = f2tf32(v.z); w1.z = f2tf32(u.w); w1.w = f2tf32(v.w);
            *(uint4*)&bA[am * 40 + ah + pg * 8]     = w0;
            *(uint4*)&bA[am * 40 + ah + pg * 8 + 4] = w1;
        }
    };
    auto cpB = [&](int chunk, int p) {
        const float* src = g_Bp + (size_t)chunk * 5120;
        const uint32_t dst = smem_u32 + (p * BUFW + 5120) * 4;
#pragma unroll
        for (int it = 0; it < 5; it++) {
            const int q = tid + it * 256;
            cp_async16(dst + q * 16, src + q * 4);
        }
        asm volatile("cp.async.commit_group;" ::: "memory");
    };
    auto compute = [&](int p) {
        const uint32_t* bA = (const uint32_t*)(sm + p * BUFW);
        const uint32_t* bB = (const uint32_t*)(sm + p * BUFW + 5120);
#pragma unroll
        for (int ks = 0; ks < 4; ks++) {
            uint32_t af[2][4], bf[8][2];
#pragma unroll
            for (int i = 0; i < 2; i++) {
                const int r = wm * 32 + i * 16 + gq;
                const uint2 lo = *(const uint2*)&bA[r * 40 + ks * 8 + 2 * tq];
                const uint2 hi = *(const uint2*)&bA[(r + 8) * 40 + ks * 8 + 2 * tq];
                af[i][0] = lo.x; af[i][1] = hi.x; af[i][2] = lo.y; af[i][3] = hi.y;
            }
#pragma unroll
            for (int j = 0; j < 8; j++) {
                const int c = wn * 64 + j * 8 + gq;
                const uint2 b = *(const uint2*)&bB[c * 40 + ks * 8 + 2 * tq];
                bf[j][0] = b.x; bf[j][1] = b.y;
            }
#pragma unroll
            for (int i = 0; i < 2; i++)
#pragma unroll
                for (int j = 0; j < 8; j++)
                    mma_tf32(acc[i][j], af[i], bf[j]);
        }
    };

    ldgA(0); cpB(0, 0); stsA(0);
    asm volatile("cp.async.wait_group 0;" ::: "memory");
    __syncthreads();
    for (int c = 0; c < 4; c++) {
        if (c + 1 < 4) { ldgA((c + 1) * 32); cpB(c + 1, (c + 1) & 1); }
        compute(c & 1);
        if (c + 1 < 4) stsA((c + 1) & 1);
        asm volatile("cp.async.wait_group 0;" ::: "memory");
        __syncthreads();
    }

#pragma unroll
    for (int i = 0; i < 2; i++)
#pragma unroll
        for (int h2 = 0; h2 < 2; h2++) {
            const int r = m0 + wm * 32 + i * 16 + gq + h2 * 8;
#pragma unroll
            for (int j = 0; j < 8; j++) {
                const int c = wn * 64 + j * 8 + tq * 2;
                *(float2*)(g_P + (size_t)r * 128 + c) =
                    make_float2(acc[i][j][h2 * 2 + 0], acc[i][j][h2 * 2 + 1]);
            }
        }
}

// ===== fused node MLP: t in smem (stride 136), then out = h + t@W2 + b2 =====
__global__ __launch_bounds__(256, 2) void gemm_fused(
    const float* __restrict__ A,
    const float* __restrict__ b1,
    const float* __restrict__ b2,
    float* __restrict__ OutH,
    const float* __restrict__ X,
    float* __restrict__ OutX)
{
    extern __shared__ float sm[];
    const int BUFW = 10240;

    if (blockIdx.x >= 512) {
        const int t0 = (blockIdx.x - 512) * 256 + threadIdx.x;
        for (int i = t0; i < BN * 3; i += 256 * 256)
            OutX[i] = X[i] + g_dx[i];
        return;
    }

    const int tid  = threadIdx.x;
    const int lane = tid & 31, warp = tid >> 5;
    const int wm = warp & 3, wn = warp >> 2;
    const int gq = lane >> 2, tq = lane & 3;
    const int m0 = blockIdx.x * 128;
    const uint32_t smem_u32 = (uint32_t)__cvta_generic_to_shared(sm);
    uint32_t* tT = (uint32_t*)(sm + 20480);   // [128][136]

    float4 ra[4];
    const int am = tid >> 1;
    const int ah = (tid & 1) * 16;

    auto ldgA = [&](int k0) {
        const int f = k0 + ah;
        const float* src = (f < 128) ? (A + (size_t)(m0 + am) * 128 + f)
                                     : (g_dh + (size_t)(m0 + am) * 64 + (f - 128));
        ra[0] = *(const float4*)(src);
        ra[1] = *(const float4*)(src + 4);
        ra[2] = *(const float4*)(src + 8);
        ra[3] = *(const float4*)(src + 12);
    };
    auto stsA = [&](int p) {
        float* bA = sm + p * BUFW;
#pragma unroll
        for (int pg = 0; pg < 2; pg++) {
            const float4 u = ra[pg * 2], v = ra[pg * 2 + 1];
            uint4 w0, w1;
            w0.x = f2tf32(u.x); w0.y = f2tf32(v.x); w0.z = f2tf32(u.y); w0.w = f2tf32(v.y);
            w1.x = f2tf32(u.z); w1.y = f2tf32(v.z); w1.z = f2tf32(u.w); w1.w = f2tf32(v.w);
            *(uint4*)&bA[am * 40 + ah + pg * 8]     = w0;
            *(uint4*)&bA[am * 40 + ah + pg * 8 + 4] = w1;
        }
    };
    auto cpB = [&](int chunk, int p) {
        const float* src = g_Bp + (size_t)chunk * 5120;
        const uint32_t dst = smem_u32 + (p * BUFW + 5120) * 4;
#pragma unroll
        for (int it = 0; it < 5; it++) {
            const int q = tid + it * 256;
            cp_async16(dst + q * 16, src + q * 4);
        }
        asm volatile("cp.async.commit_group;" ::: "memory");
    };

    const int sl0 = ((2 * tq) & 3) * 2 + ((2 * tq) >> 2);
    const int sl1 = ((2 * tq + 1) & 3) * 2 + ((2 * tq + 1) >> 2);

    // ---------------- phase 1 ----------------
    {
        float acc[2][8][4];
#pragma unroll
        for (int i = 0; i < 2; i++)
#pragma unroll
            for (int j = 0; j < 8; j++)
#pragma unroll
                for (int q = 0; q < 4; q++) acc[i][j][q] = 0.f;

        auto compute = [&](int p) {
            const uint32_t* bA = (const uint32_t*)(sm + p * BUFW);
            const uint32_t* bB = (const uint32_t*)(sm + p * BUFW + 5120);
#pragma unroll
            for (int ks = 0; ks < 4; ks++) {
                uint32_t af[2][4], bf[8][2];
#pragma unroll
                for (int i = 0; i < 2; i++) {
                    const int r = wm * 32 + i * 16 + gq;
                    const uint2 lo = *(const uint2*)&bA[r * 40 + ks * 8 + 2 * tq];
                    const uint2 hi = *(const uint2*)&bA[(r + 8) * 40 + ks * 8 + 2 * tq];
                    af[i][0] = lo.x; af[i][1] = hi.x; af[i][2] = lo.y; af[i][3] = hi.y;
                }
#pragma unroll
                for (int j = 0; j < 8; j++) {
                    const int c = wn * 64 + j * 8 + gq;
                    const uint2 b = *(const uint2*)&bB[c * 40 + ks * 8 + 2 * tq];
                    bf[j][0] = b.x; bf[j][1] = b.y;
                }
#pragma unroll
                for (int i = 0; i < 2; i++)
#pragma unroll
                    for (int j = 0; j < 8; j++)
                        mma_tf32(acc[i][j], af[i], bf[j]);
            }
        };

        ldgA(0); cpB(4, 0); stsA(0);
        asm volatile("cp.async.wait_group 0;" ::: "memory");
        __syncthreads();
        for (int c = 0; c < 6; c++) {
            if (c + 1 < 6) { ldgA((c + 1) * 32); cpB(5 + c, (c + 1) & 1); }
            compute(c & 1);
            if (c + 1 < 6) stsA((c + 1) & 1);
            asm volatile("cp.async.wait_group 0;" ::: "memory");
            __syncthreads();
        }

#pragma unroll
        for (int i = 0; i < 2; i++)
#pragma unroll
            for (int h2 = 0; h2 < 2; h2++) {
                const int rl = wm * 32 + i * 16 + gq + h2 * 8;
#pragma unroll
                for (int j = 0; j < 8; j++) {
                    const int c = wn * 64 + j * 8 + tq * 2;
                    const float v0 = silu_f(acc[i][j][h2 * 2 + 0] + __ldg(b1 + c));
                    const float v1 = silu_f(acc[i][j][h2 * 2 + 1] + __ldg(b1 + c + 1));
                    uint32_t* d = &tT[rl * 136 + (c >> 3) * 8];
                    d[sl0] = f2tf32(v0);
                    d[sl1] = f2tf32(v1);
                }
            }
    }
    __syncthreads();

    // ---------------- phase 2 ----------------
    {
        float acc[2][8][4];
#pragma unroll
        for (int i = 0; i < 2; i++)
#pragma unroll
            for (int j = 0; j < 8; j++)
#pragma unroll
                for (int q = 0; q < 4; q++) acc[i][j][q] = 0.f;

        cpB(10, 0);
        asm volatile("cp.async.wait_group 0;" ::: "memory");
        __syncthreads();
        for (int kc = 0; kc < 4; kc++) {
            if (kc + 1 < 4) cpB(11 + kc, (kc + 1) & 1);
            const uint32_t* bB = (const uint32_t*)(sm + (kc & 1) * BUFW + 5120);
#pragma unroll
            for (int ks = 0; ks < 4; ks++) {
                const int kg = kc * 4 + ks;
                uint32_t af[2][4], bf[8][2];
#pragma unroll
                for (int i = 0; i < 2; i++) {
                    const int r = wm * 32 + i * 16 + gq;
                    const uint2 lo = *(const uint2*)&tT[r * 136 + kg * 8 + 2 * tq];
                    const uint2 hi = *(const uint2*)&tT[(r + 8) * 136 + kg * 8 + 2 * tq];
                    af[i][0] = lo.x; af[i][1] = hi.x; af[i][2] = lo.y; af[i][3] = hi.y;
                }
#pragma unroll
                for (int j = 0; j < 8; j++) {
                    const int c = wn * 64 + j * 8 + gq;
                    const uint2 b = *(const uint2*)&bB[c * 40 + ks * 8 + 2 * tq];
                    bf[j][0] = b.x; bf[j][1] = b.y;
                }
#pragma unroll
                for (int i = 0; i < 2; i++)
#pragma unroll
                    for (int j = 0; j < 8; j++)
                        mma_tf32(acc[i][j], af[i], bf[j]);
            }
            asm volatile("cp.async.wait_group 0;" ::: "memory");
            __syncthreads();
        }

#pragma unroll
        for (int i = 0; i < 2; i++)
#pragma unroll
            for (int h2 = 0; h2 < 2; h2++) {
                const int r = m0 + wm * 32 + i * 16 + gq + h2 * 8;
#pragma unroll
                for (int j = 0; j < 8; j++) {
                    const int c = wn * 64 + j * 8 + tq * 2;
                    const size_t base = (size_t)r * 128 + c;
                    const float2 hh = *(const float2*)(A + base);
                    const float v0 = acc[i][j][h2 * 2 + 0] + __ldg(b2 + c) + hh.x;
                    const float v1 = acc[i][j][h2 * 2 + 1] + __ldg(b2 + c + 1) + hh.y;
                    *(float2*)(OutH + base) = make_float2(v0, v1);
                }
            }
    }
}

// -------- edge kernel: 128 edges/block, 256 threads, 4 CTAs/SM, K-split -----
__global__ __launch_bounds__(256, 4) void edge_kernel(
    const float* __restrict__ x,
    const int*   __restrict__ edges,
    const float* __restrict__ W1,
    const float* __restrict__ b1,
    const float* __restrict__ b2,
    const float* __restrict__ pxw)
{
    extern __shared__ float dyn[];
    float* sW2 = dyn;
    float* sM  = dyn + 64 * 72;
    const uint32_t* sW2u = (const uint32_t*)sW2;
    const uint32_t* sMu  = (const uint32_t*)sM;

    __shared__ int   sSrc[EPB], sDst[EPB];
    __shared__ float sD2[EPB];
    __shared__ float sDirx[EPB], sDiry[EPB], sDirz[EPB];
    __shared__ float sB1[64], sB2[64], sPx[64], sW1r[64];

    const int tid  = threadIdx.x;
    const int lane = tid & 31, warp = tid >> 5;
    const int gq = lane >> 2, tq = lane & 3;
    const int e0 = blockIdx.x * EPB;

    if (tid < EPB) {
        const int eg = e0 + tid;
        const int b  = eg >> 16;
        const int2 sd = ((const int2*)edges)[eg];
        const int gi = b * NPB + sd.x;
        const int gj = b * NPB + sd.y;
        sSrc[tid] = gi; sDst[tid] = gj;
        const float xi0 = x[(size_t)gi * 3 + 0], xi1 = x[(size_t)gi * 3 + 1], xi2 = x[(size_t)gi * 3 + 2];
        const float xj0 = x[(size_t)gj * 3 + 0], xj1 = x[(size_t)gj * 3 + 1], xj2 = x[(size_t)gj * 3 + 2];
        const float d0 = xi0 - xj0, d1 = xi1 - xj1, d2c = xi2 - xj2;
        float d2 = d0 * d0 + d1 * d1 + d2c * d2c;
        d2 = fmaxf(d2, 1e-12f);
        sD2[tid] = d2;
        const float inv = 1.0f / (sqrtf(d2) + 1e-8f);
        sDirx[tid] = d0 * inv; sDiry[tid] = d1 * inv; sDirz[tid] = d2c * inv;
    }
    if (tid >= 128 && tid < 192) {
        const int t = tid - 128;
        sB1[t] = b1[t];
        sB2[t] = b2[t];
        sPx[t] = pxw[t];
        sW1r[t] = W1[256 * 64 + t];
    }
#pragma unroll
    for (int it = 0; it < 5; it++) {
        const int q = tid + it * 256;
        if (q < 1152) *(float4*)&sW2[q * 4] = *(const float4*)&g_W2p[q * 4];
    }
    __syncthreads();

    float acc[8][4];
#pragma unroll
    for (int j = 0; j < 8; j++)
#pragma unroll
        for (int q = 0; q < 4; q++) acc[j][q] = 0.f;

#pragma unroll
    for (int h = 0; h < 2; h++) {
#pragma unroll
        for (int it = 0; it < 4; ++it) {
            const int idx = it * 256 + tid;
            const int e = idx >> 3, qp = idx & 7;
            const int k = h * 32 + qp * 4;
            const float4 a = *(const float4*)(g_P + (size_t)sSrc[e] * 128 + k);
            const float4 b = *(const float4*)(g_P + (size_t)sDst[e] * 128 + 64 + k);
            const float4 wv = *(const float4*)&sW1r[k];
            const float4 bv = *(const float4*)&sB1[k];
            const float d2 = sD2[e];
            float* dst = &sM[e * 36 + (qp >> 1) * 8 + (qp & 1)];
            dst[0] = __uint_as_float(f2tf32(silu_f(a.x + b.x + d2 * wv.x + bv.x)));
            dst[2] = __uint_as_float(f2tf32(silu_f(a.y + b.y + d2 * wv.y + bv.y)));
            dst[4] = __uint_as_float(f2tf32(silu_f(a.z + b.z + d2 * wv.z + bv.z)));
            dst[6] = __uint_as_float(f2tf32(silu_f(a.w + b.w + d2 * wv.w + bv.w)));
        }
        __syncthreads();

#pragma unroll
        for (int ksl = 0; ksl < 4; ksl++) {
            const int ks = h * 4 + ksl;
            uint32_t af[4], bf[2];
            const int r = warp * 16 + gq;
            const uint2 lo = *(const uint2*)&sMu[r * 36 + ksl * 8 + 2 * tq];
            const uint2 hi = *(const uint2*)&sMu[(r + 8) * 36 + ksl * 8 + 2 * tq];
            af[0] = lo.x; af[1] = hi.x; af[2] = lo.y; af[3] = hi.y;
#pragma unroll
            for (int j = 0; j < 8; j++) {
                const int c = j * 8 + gq;
                const uint2 b = *(const uint2*)&sW2u[c * 72 + ks * 8 + 2 * tq];
                bf[0] = b.x; bf[1] = b.y;
                mma_tf32(acc[j], af, bf);
            }
        }
        if (h == 0) __syncthreads();
    }

    const int r0 = warp * 16 + gq;
    const int n0 = sSrc[r0], n1 = sSrc[r0 + 8];
    float part0 = 0.f, part1 = 0.f;
#pragma unroll
    for (int j = 0; j < 8; j++) {
        const int c = j * 8 + tq * 2;
        const float bb0 = sB2[c], bb1 = sB2[c + 1];
        const float px0 = sPx[c], px1 = sPx[c + 1];
        const float v0 = silu_f(acc[j][0] + bb0);
        const float v1 = silu_f(acc[j][1] + bb1);
        const float v2 = silu_f(acc[j][2] + bb0);
        const float v3 = silu_f(acc[j][3] + bb1);
        part0 += v0 * px0 + v1 * px1;
        part1 += v2 * px0 + v3 * px1;
        red_add_v2(g_dh + (size_t)n0 * 64 + c, v0, v1);
        red_add_v2(g_dh + (size_t)n1 * 64 + c, v2, v3);
    }
    part0 += __shfl_xor_sync(0xffffffffu, part0, 1);
    part0 += __shfl_xor_sync(0xffffffffu, part0, 2);
    part1 += __shfl_xor_sync(0xffffffffu, part1, 1);
    part1 += __shfl_xor_sync(0xffffffffu, part1, 2);
    if (tq == 0) {
        atomicAdd(&g_dx[(size_t)n0 * 3 + 0], part0 * sDirx[r0]);
        atomicAdd(&g_dx[(size_t)n0 * 3 + 1], part0 * sDiry[r0]);
        atomicAdd(&g_dx[(size_t)n0 * 3 + 2], part0 * sDirz[r0]);
        atomicAdd(&g_dx[(size_t)n1 * 3 + 0], part1 * sDirx[r0 + 8]);
        atomicAdd(&g_dx[(size_t)n1 * 3 + 1], part1 * sDiry[r0 + 8]);
        atomicAdd(&g_dx[(size_t)n1 * 3 + 2], part1 * sDirz[r0 + 8]);
    }
}

// ---------------- launch ----------------
extern "C" void kernel_launch(void* const* d_in, const int* in_sizes, int n_in,
                              void* d_out, int out_size) {
    const float* x   = (const float*)d_in[0];
    const float* h   = (const float*)d_in[1];
    const int*   ei  = (const int*)d_in[2];
    const float* pw1 = (const float*)d_in[3];
    const float* pb1 = (const float*)d_in[4];
    const float* pw2 = (const float*)d_in[5];
    const float* pb2 = (const float*)d_in[6];
    const float* pxw = (const float*)d_in[7];
    const float* hw1 = (const float*)d_in[8];
    const float* hb1 = (const float*)d_in[9];
    const float* hw2 = (const float*)d_in[10];
    const float* hb2 = (const float*)d_in[11];

    float* out   = (float*)d_out;
    float* out_x = out;
    float* out_h = out + (size_t)BN * 3;

    const int GSMEM = 2 * 10240 * (int)sizeof(float);                  // 81920 B
    const int FSMEM = (20480 + 128 * 136) * (int)sizeof(float);        // 151552 B
    const int EDGE_SMEM = (64 * 72 + EPB * 36) * (int)sizeof(float);   // 36864 B
    cudaFuncSetAttribute(gemm_p, cudaFuncAttributeMaxDynamicSharedMemorySize, GSMEM);
    cudaFuncSetAttribute(gemm_fused, cudaFuncAttributeMaxDynamicSharedMemorySize, FSMEM);
    cudaFuncSetAttribute(edge_kernel, cudaFuncAttributeMaxDynamicSharedMemorySize, EDGE_SMEM);

    prep_kernel<<<256, 256>>>(pw1, hw1, hw2, pw2);
    gemm_p<<<BN / 128, 256, GSMEM>>>(h);
    edge_kernel<<<NE / EPB, 256, EDGE_SMEM>>>(x, ei, pw1, pb1, pb2, pxw);
    gemm_fused<<<BN / 128 + 256, 256, FSMEM>>>(h, hb1, hb2, out_h, x, out_x);
}

// round 8
// speedup vs baseline: 1.1379x; 1.1379x over previous
#include <cuda_runtime.h>
#include <math.h>
#include <stdint.h>

#define BN   65536
#define NPB  16384
#define NE   262144
#define EPB  128

__device__ __align__(16) float g_P [(size_t)BN * 128];
__device__ __align__(16) float g_dh[(size_t)BN * 64];
__device__ __align__(16) float g_dx[(size_t)BN * 3];
__device__ __align__(16) float g_Bp[14 * 128 * 40];
__device__ __align__(16) float g_W2p[64 * 72];

__device__ __forceinline__ float silu_f(float v) {
    return v * (1.0f / (1.0f + __expf(-v)));
}
__device__ __forceinline__ uint32_t f2tf32(float f) {
    uint32_t r;
    asm("cvt.rna.tf32.f32 %0, %1;" : "=r"(r) : "f"(f));
    return r;
}
__device__ __forceinline__ void mma_tf32(float* c, const uint32_t* a, const uint32_t* b) {
    asm volatile("mma.sync.aligned.m16n8k8.row.col.f32.tf32.tf32.f32 "
        "{%0,%1,%2,%3}, {%4,%5,%6,%7}, {%8,%9}, {%0,%1,%2,%3};"
        : "+f"(c[0]), "+f"(c[1]), "+f"(c[2]), "+f"(c[3])
        : "r"(a[0]), "r"(a[1]), "r"(a[2]), "r"(a[3]), "r"(b[0]), "r"(b[1]));
}
__device__ __forceinline__ void red_add_v2(float* p, float a, float b) {
    asm volatile("red.global.add.v2.f32 [%0], {%1,%2};"
                 :: "l"(p), "f"(a), "f"(b) : "memory");
}
__device__ __forceinline__ void cp_async16(uint32_t dst, const void* src) {
    asm volatile("cp.async.cg.shared.global [%0], [%1], 16;" :: "r"(dst), "l"(src));
}

__global__ void prep_kernel(const float* __restrict__ pw1,
                            const float* __restrict__ hw1,
                            const float* __restrict__ hw2,
                            const float* __restrict__ pw2)
{
    const int stride = gridDim.x * blockDim.x;
    const int idx0 = blockIdx.x * blockDim.x + threadIdx.x;
    {
        float4 z = make_float4(0.f, 0.f, 0.f, 0.f);
        const size_t n1 = (size_t)BN * 16;
        const size_t n2 = (size_t)BN * 3 / 4;
        const size_t total = n1 + n2;
        for (size_t i = idx0; i < total; i += stride) {
            if (i < n1) ((float4*)g_dh)[i] = z;
            else        ((float4*)g_dx)[i - n1] = z;
        }
    }
    for (int i = idx0; i < 14 * 128 * 40; i += stride) {
        const int w = i % 40, n = (i / 40) & 127, c = i / (40 * 128);
        float v = 0.f;
        if (w < 32) {
            const int g = w >> 3, s = w & 7;
            const int k8 = (s >> 1) + ((s & 1) << 2);
            if (c < 4) {
                const int k = c * 32 + g * 8 + k8;
                v = (n < 64) ? pw1[k * 64 + n] : pw1[(128 + k) * 64 + (n - 64)];
            } else if (c < 10) {
                const int k = (c - 4) * 32 + g * 8 + k8;
                v = hw1[k * 128 + n];
            } else {
                const int k = (c - 10) * 32 + g * 8 + k8;
                v = hw2[k * 128 + n];
            }
            v = __uint_as_float(f2tf32(v));
        }
        g_Bp[i] = v;
    }
    for (int i = idx0; i < 64 * 72; i += stride) {
        const int w = i % 72, n = i / 72;
        float v = 0.f;
        if (w < 64) {
            const int g = w >> 3, s = w & 7;
            const int k = g * 8 + (s >> 1) + ((s & 1) << 2);
            v = __uint_as_float(f2tf32(pw2[k * 64 + n]));
        }
        g_W2p[i] = v;
    }
}

// ============ gemm_p: CTA 128x128, warp 32x64, double-buffered ==============
__global__ __launch_bounds__(256, 2) void gemm_p(const float* __restrict__ A)
{
    extern __shared__ float sm[];
    const int BUFW = 10240;
    const int tid  = threadIdx.x;
    const int lane = tid & 31, warp = tid >> 5;
    const int wm = warp & 3, wn = warp >> 2;
    const int gq = lane >> 2, tq = lane & 3;
    const int m0 = blockIdx.x * 128;
    const uint32_t smem_u32 = (uint32_t)__cvta_generic_to_shared(sm);

    float acc[2][8][4];
#pragma unroll
    for (int i = 0; i < 2; i++)
#pragma unroll
        for (int j = 0; j < 8; j++)
#pragma unroll
            for (int q = 0; q < 4; q++) acc[i][j][q] = 0.f;

    float4 ra[4];
    const int am = tid >> 1;
    const int ah = (tid & 1) * 16;

    auto ldgA = [&](int k0) {
        const float* src = A + (size_t)(m0 + am) * 128 + k0 + ah;
        ra[0] = *(const float4*)(src);
        ra[1] = *(const float4*)(src + 4);
        ra[2] = *(const float4*)(src + 8);
        ra[3] = *(const float4*)(src + 12);
    };
    auto stsA = [&](int p) {
        float* bA = sm + p * BUFW;
#pragma unroll
        for (int pg = 0; pg < 2; pg++) {
            const float4 u = ra[pg * 2], v = ra[pg * 2 + 1];
            uint4 w0, w1;
            w0.x = f2tf32(u.x); w0.y = f2tf32(v.x); w0.z = f2tf32(u.y); w0.w = f2tf32(v.y);
            w1.x = f2tf32(u.z); w1.y = f2tf32(v.z); w1.z = f2tf32(u.w); w1.w = f2tf32(v.w);
            *(uint4*)&bA[am * 40 + ah + pg * 8]     = w0;
            *(uint4*)&bA[am * 40 + ah + pg * 8 + 4] = w1;
        }
    };
    auto cpB = [&](int chunk, int p) {
        const float* src = g_Bp + (size_t)chunk * 5120;
        const uint32_t dst = smem_u32 + (p * BUFW + 5120) * 4;
#pragma unroll
        for (int it = 0; it < 5; it++) {
            const int q = tid + it * 256;
            cp_async16(dst + q * 16, src + q * 4);
        }
        asm volatile("cp.async.commit_group;" ::: "memory");
    };
    auto compute = [&](int p) {
        const uint32_t* bA = (const uint32_t*)(sm + p * BUFW);
        const uint32_t* bB = (const uint32_t*)(sm + p * BUFW + 5120);
#pragma unroll
        for (int ks = 0; ks < 4; ks++) {
            uint32_t af[2][4], bf[8][2];
#pragma unroll
            for (int i = 0; i < 2; i++) {
                const int r = wm * 32 + i * 16 + gq;
                const uint2 lo = *(const uint2*)&bA[r * 40 + ks * 8 + 2 * tq];
                const uint2 hi = *(const uint2*)&bA[(r + 8) * 40 + ks * 8 + 2 * tq];
                af[i][0] = lo.x; af[i][1] = hi.x; af[i][2] = lo.y; af[i][3] = hi.y;
            }
#pragma unroll
            for (int j = 0; j < 8; j++) {
                const int c = wn * 64 + j * 8 + gq;
                const uint2 b = *(const uint2*)&bB[c * 40 + ks * 8 + 2 * tq];
                bf[j][0] = b.x; bf[j][1] = b.y;
            }
#pragma unroll
            for (int i = 0; i < 2; i++)
#pragma unroll
                for (int j = 0; j < 8; j++)
                    mma_tf32(acc[i][j], af[i], bf[j]);
        }
    };

    ldgA(0); cpB(0, 0); stsA(0);
    asm volatile("cp.async.wait_group 0;" ::: "memory");
    __syncthreads();
    for (int c = 0; c < 4; c++) {
        if (c + 1 < 4) { ldgA((c + 1) * 32); cpB(c + 1, (c + 1) & 1); }
        compute(c & 1);
        if (c + 1 < 4) stsA((c + 1) & 1);
        asm volatile("cp.async.wait_group 0;" ::: "memory");
        __syncthreads();
    }

#pragma unroll
    for (int i = 0; i < 2; i++)
#pragma unroll
        for (int h2 = 0; h2 < 2; h2++) {
            const int r = m0 + wm * 32 + i * 16 + gq + h2 * 8;
#pragma unroll
            for (int j = 0; j < 8; j++) {
                const int c = wn * 64 + j * 8 + tq * 2;
                *(float2*)(g_P + (size_t)r * 128 + c) =
                    make_float2(acc[i][j][h2 * 2 + 0], acc[i][j][h2 * 2 + 1]);
            }
        }
}

// ===== fused node MLP, 2 CTAs/SM via smem overlay ===========================
// layout (words): B0 @0, B1 @5120, A_p @10240+p*5120, tT overlays @10240
// (tT: [128][136] uint32 = 17408 words; total 27648 words = 110592 B)
__global__ __launch_bounds__(256, 2) void gemm_fused(
    const float* __restrict__ A,
    const float* __restrict__ b1,
    const float* __restrict__ b2,
    float* __restrict__ OutH,
    const float* __restrict__ X,
    float* __restrict__ OutX)
{
    extern __shared__ float sm[];

    if (blockIdx.x >= 512) {
        const int t0 = (blockIdx.x - 512) * 256 + threadIdx.x;
        for (int i = t0; i < BN * 3; i += 256 * 256)
            OutX[i] = X[i] + g_dx[i];
        return;
    }

    const int tid  = threadIdx.x;
    const int lane = tid & 31, warp = tid >> 5;
    const int wm = warp & 3, wn = warp >> 2;
    const int gq = lane >> 2, tq = lane & 3;
    const int m0 = blockIdx.x * 128;
    const uint32_t smem_u32 = (uint32_t)__cvta_generic_to_shared(sm);
    uint32_t* tT = (uint32_t*)(sm + 10240);   // [128][136], overlays A slots

    float4 ra[4];
    const int am = tid >> 1;
    const int ah = (tid & 1) * 16;

    auto ldgA = [&](int k0) {
        const int f = k0 + ah;
        const float* src = (f < 128) ? (A + (size_t)(m0 + am) * 128 + f)
                                     : (g_dh + (size_t)(m0 + am) * 64 + (f - 128));
        ra[0] = *(const float4*)(src);
        ra[1] = *(const float4*)(src + 4);
        ra[2] = *(const float4*)(src + 8);
        ra[3] = *(const float4*)(src + 12);
    };
    auto stsA = [&](int p) {
        float* bA = sm + 10240 + p * 5120;
#pragma unroll
        for (int pg = 0; pg < 2; pg++) {
            const float4 u = ra[pg * 2], v = ra[pg * 2 + 1];
            uint4 w0, w1;
            w0.x = f2tf32(u.x); w0.y = f2tf32(v.x); w0.z = f2tf32(u.y); w0.w = f2tf32(v.y);
            w1.x = f2tf32(u.z); w1.y = f2tf32(v.z); w1.z = f2tf32(u.w); w1.w = f2tf32(v.w);
            *(uint4*)&bA[am * 40 + ah + pg * 8]     = w0;
            *(uint4*)&bA[am * 40 + ah + pg * 8 + 4] = w1;
        }
    };
    auto cpB = [&](int chunk, int p) {
        const float* src = g_Bp + (size_t)chunk * 5120;
        const uint32_t dst = smem_u32 + (p * 5120) * 4;
#pragma unroll
        for (int it = 0; it < 5; it++) {
            const int q = tid + it * 256;
            cp_async16(dst + q * 16, src + q * 4);
        }
        asm volatile("cp.async.commit_group;" ::: "memory");
    };

    const int sl0 = ((2 * tq) & 3) * 2 + ((2 * tq) >> 2);
    const int sl1 = ((2 * tq + 1) & 3) * 2 + ((2 * tq + 1) >> 2);

    // ---------------- phase 1: t = silu([h|dh]@W1 + b1) ----------------
    {
        float acc[2][8][4];
#pragma unroll
        for (int i = 0; i < 2; i++)
#pragma unroll
            for (int j = 0; j < 8; j++)
#pragma unroll
                for (int q = 0; q < 4; q++) acc[i][j][q] = 0.f;

        auto compute = [&](int p) {
            const uint32_t* bA = (const uint32_t*)(sm + 10240 + p * 5120);
            const uint32_t* bB = (const uint32_t*)(sm + p * 5120);
#pragma unroll
            for (int ks = 0; ks < 4; ks++) {
                uint32_t af[2][4], bf[8][2];
#pragma unroll
                for (int i = 0; i < 2; i++) {
                    const int r = wm * 32 + i * 16 + gq;
                    const uint2 lo = *(const uint2*)&bA[r * 40 + ks * 8 + 2 * tq];
                    const uint2 hi = *(const uint2*)&bA[(r + 8) * 40 + ks * 8 + 2 * tq];
                    af[i][0] = lo.x; af[i][1] = hi.x; af[i][2] = lo.y; af[i][3] = hi.y;
                }
#pragma unroll
                for (int j = 0; j < 8; j++) {
                    const int c = wn * 64 + j * 8 + gq;
                    const uint2 b = *(const uint2*)&bB[c * 40 + ks * 8 + 2 * tq];
                    bf[j][0] = b.x; bf[j][1] = b.y;
                }
#pragma unroll
                for (int i = 0; i < 2; i++)
#pragma unroll
                    for (int j = 0; j < 8; j++)
                        mma_tf32(acc[i][j], af[i], bf[j]);
            }
        };

        ldgA(0); cpB(4, 0); stsA(0);
        asm volatile("cp.async.wait_group 0;" ::: "memory");
        __syncthreads();
        for (int c = 0; c < 6; c++) {
            if (c + 1 < 6) { ldgA((c + 1) * 32); cpB(5 + c, (c + 1) & 1); }
            compute(c & 1);
            if (c + 1 < 6) stsA((c + 1) & 1);
            asm volatile("cp.async.wait_group 0;" ::: "memory");
            __syncthreads();
        }

        // epilogue 1: silu(+b1) -> tT (overlays dead A slots; loop ended with sync)
#pragma unroll
        for (int i = 0; i < 2; i++)
#pragma unroll
            for (int h2 = 0; h2 < 2; h2++) {
                const int rl = wm * 32 + i * 16 + gq + h2 * 8;
#pragma unroll
                for (int j = 0; j < 8; j++) {
                    const int c = wn * 64 + j * 8 + tq * 2;
                    const float v0 = silu_f(acc[i][j][h2 * 2 + 0] + __ldg(b1 + c));
                    const float v1 = silu_f(acc[i][j][h2 * 2 + 1] + __ldg(b1 + c + 1));
                    uint32_t* d = &tT[rl * 136 + (c >> 3) * 8];
                    d[sl0] = f2tf32(v0);
                    d[sl1] = f2tf32(v1);
                }
            }
    }
    __syncthreads();

    // ---------------- phase 2: out = h + t@W2 + b2 ----------------
    {
        float acc[2][8][4];
#pragma unroll
        for (int i = 0; i < 2; i++)
#pragma unroll
            for (int j = 0; j < 8; j++)
#pragma unroll
                for (int q = 0; q < 4; q++) acc[i][j][q] = 0.f;

        cpB(10, 0);
        asm volatile("cp.async.wait_group 0;" ::: "memory");
        __syncthreads();
        for (int kc = 0; kc < 4; kc++) {
            if (kc + 1 < 4) cpB(11 + kc, (kc + 1) & 1);
            const uint32_t* bB = (const uint32_t*)(sm + (kc & 1) * 5120);
#pragma unroll
            for (int ks = 0; ks < 4; ks++) {
                const int kg = kc * 4 + ks;
                uint32_t af[2][4], bf[8][2];
#pragma unroll
                for (int i = 0; i < 2; i++) {
                    const int r = wm * 32 + i * 16 + gq;
                    const uint2 lo = *(const uint2*)&tT[r * 136 + kg * 8 + 2 * tq];
                    const uint2 hi = *(const uint2*)&tT[(r + 8) * 136 + kg * 8 + 2 * tq];
                    af[i][0] = lo.x; af[i][1] = hi.x; af[i][2] = lo.y; af[i][3] = hi.y;
                }
#pragma unroll
                for (int j = 0; j < 8; j++) {
                    const int c = wn * 64 + j * 8 + gq;
                    const uint2 b = *(const uint2*)&bB[c * 40 + ks * 8 + 2 * tq];
                    bf[j][0] = b.x; bf[j][1] = b.y;
                }
#pragma unroll
                for (int i = 0; i < 2; i++)
#pragma unroll
                    for (int j = 0; j < 8; j++)
                        mma_tf32(acc[i][j], af[i], bf[j]);
            }
            asm volatile("cp.async.wait_group 0;" ::: "memory");
            __syncthreads();
        }

#pragma unroll
        for (int i = 0; i < 2; i++)
#pragma unroll
            for (int h2 = 0; h2 < 2; h2++) {
                const int r = m0 + wm * 32 + i * 16 + gq + h2 * 8;
#pragma unroll
                for (int j = 0; j < 8; j++) {
                    const int c = wn * 64 + j * 8 + tq * 2;
                    const size_t base = (size_t)r * 128 + c;
                    const float2 hh = *(const float2*)(A + base);
                    const float v0 = acc[i][j][h2 * 2 + 0] + __ldg(b2 + c) + hh.x;
                    const float v1 = acc[i][j][h2 * 2 + 1] + __ldg(b2 + c + 1) + hh.y;
                    *(float2*)(OutH + base) = make_float2(v0, v1);
                }
            }
    }
}

// -------- edge kernel: 128 edges/block, 256 threads, 4 CTAs/SM, K-split -----
__global__ __launch_bounds__(256, 4) void edge_kernel(
    const float* __restrict__ x,
    const int*   __restrict__ edges,
    const float* __restrict__ W1,
    const float* __restrict__ b1,
    const float* __restrict__ b2,
    const float* __restrict__ pxw)
{
    extern __shared__ float dyn[];
    float* sW2 = dyn;
    float* sM  = dyn + 64 * 72;
    const uint32_t* sW2u = (const uint32_t*)sW2;
    const uint32_t* sMu  = (const uint32_t*)sM;

    __shared__ int   sSrc[EPB], sDst[EPB];
    __shared__ float sD2[EPB];
    __shared__ float sDirx[EPB], sDiry[EPB], sDirz[EPB];
    __shared__ float sB1[64], sB2[64], sPx[64], sW1r[64];

    const int tid  = threadIdx.x;
    const int lane = tid & 31, warp = tid >> 5;
    const int gq = lane >> 2, tq = lane & 3;
    const int e0 = blockIdx.x * EPB;

    if (tid < EPB) {
        const int eg = e0 + tid;
        const int b  = eg >> 16;
        const int2 sd = ((const int2*)edges)[eg];
        const int gi = b * NPB + sd.x;
        const int gj = b * NPB + sd.y;
        sSrc[tid] = gi; sDst[tid] = gj;
        const float xi0 = x[(size_t)gi * 3 + 0], xi1 = x[(size_t)gi * 3 + 1], xi2 = x[(size_t)gi * 3 + 2];
        const float xj0 = x[(size_t)gj * 3 + 0], xj1 = x[(size_t)gj * 3 + 1], xj2 = x[(size_t)gj * 3 + 2];
        const float d0 = xi0 - xj0, d1 = xi1 - xj1, d2c = xi2 - xj2;
        float d2 = d0 * d0 + d1 * d1 + d2c * d2c;
        d2 = fmaxf(d2, 1e-12f);
        sD2[tid] = d2;
        const float inv = 1.0f / (sqrtf(d2) + 1e-8f);
        sDirx[tid] = d0 * inv; sDiry[tid] = d1 * inv; sDirz[tid] = d2c * inv;
    }
    if (tid >= 128 && tid < 192) {
        const int t = tid - 128;
        sB1[t] = b1[t];
        sB2[t] = b2[t];
        sPx[t] = pxw[t];
        sW1r[t] = W1[256 * 64 + t];
    }
#pragma unroll
    for (int it = 0; it < 5; it++) {
        const int q = tid + it * 256;
        if (q < 1152) *(float4*)&sW2[q * 4] = *(const float4*)&g_W2p[q * 4];
    }
    __syncthreads();

    float acc[8][4];
#pragma unroll
    for (int j = 0; j < 8; j++)
#pragma unroll
        for (int q = 0; q < 4; q++) acc[j][q] = 0.f;

#pragma unroll
    for (int h = 0; h < 2; h++) {
#pragma unroll
        for (int it = 0; it < 4; ++it) {
            const int idx = it * 256 + tid;
            const int e = idx >> 3, qp = idx & 7;
            const int k = h * 32 + qp * 4;
            const float4 a = *(const float4*)(g_P + (size_t)sSrc[e] * 128 + k);
            const float4 b = *(const float4*)(g_P + (size_t)sDst[e] * 128 + 64 + k);
            const float4 wv = *(const float4*)&sW1r[k];
            const float4 bv = *(const float4*)&sB1[k];
            const float d2 = sD2[e];
            float* dst = &sM[e * 36 + (qp >> 1) * 8 + (qp & 1)];
            dst[0] = __uint_as_float(f2tf32(silu_f(a.x + b.x + d2 * wv.x + bv.x)));
            dst[2] = __uint_as_float(f2tf32(silu_f(a.y + b.y + d2 * wv.y + bv.y)));
            dst[4] = __uint_as_float(f2tf32(silu_f(a.z + b.z + d2 * wv.z + bv.z)));
            dst[6] = __uint_as_float(f2tf32(silu_f(a.w + b.w + d2 * wv.w + bv.w)));
        }
        __syncthreads();

#pragma unroll
        for (int ksl = 0; ksl < 4; ksl++) {
            const int ks = h * 4 + ksl;
            uint32_t af[4], bf[2];
            const int r = warp * 16 + gq;
            const uint2 lo = *(const uint2*)&sMu[r * 36 + ksl * 8 + 2 * tq];
            const uint2 hi = *(const uint2*)&sMu[(r + 8) * 36 + ksl * 8 + 2 * tq];
            af[0] = lo.x; af[1] = hi.x; af[2] = lo.y; af[3] = hi.y;
#pragma unroll
            for (int j = 0; j < 8; j++) {
                const int c = j * 8 + gq;
                const uint2 b = *(const uint2*)&sW2u[c * 72 + ks * 8 + 2 * tq];
                bf[0] = b.x; bf[1] = b.y;
                mma_tf32(acc[j], af, bf);
            }
        }
        if (h == 0) __syncthreads();
    }

    const int r0 = warp * 16 + gq;
    const int n0 = sSrc[r0], n1 = sSrc[r0 + 8];
    float part0 = 0.f, part1 = 0.f;
#pragma unroll
    for (int j = 0; j < 8; j++) {
        const int c = j * 8 + tq * 2;
        const float bb0 = sB2[c], bb1 = sB2[c + 1];
        const float px0 = sPx[c], px1 = sPx[c + 1];
        const float v0 = silu_f(acc[j][0] + bb0);
        const float v1 = silu_f(acc[j][1] + bb1);
        const float v2 = silu_f(acc[j][2] + bb0);
        const float v3 = silu_f(acc[j][3] + bb1);
        part0 += v0 * px0 + v1 * px1;
        part1 += v2 * px0 + v3 * px1;
        red_add_v2(g_dh + (size_t)n0 * 64 + c, v0, v1);
        red_add_v2(g_dh + (size_t)n1 * 64 + c, v2, v3);
    }
    part0 += __shfl_xor_sync(0xffffffffu, part0, 1);
    part0 += __shfl_xor_sync(0xffffffffu, part0, 2);
    part1 += __shfl_xor_sync(0xffffffffu, part1, 1);
    part1 += __shfl_xor_sync(0xffffffffu, part1, 2);
    if (tq == 0) {
        atomicAdd(&g_dx[(size_t)n0 * 3 + 0], part0 * sDirx[r0]);
        atomicAdd(&g_dx[(size_t)n0 * 3 + 1], part0 * sDiry[r0]);
        atomicAdd(&g_dx[(size_t)n0 * 3 + 2], part0 * sDirz[r0]);
        atomicAdd(&g_dx[(size_t)n1 * 3 + 0], part1 * sDirx[r0 + 8]);
        atomicAdd(&g_dx[(size_t)n1 * 3 + 1], part1 * sDiry[r0 + 8]);
        atomicAdd(&g_dx[(size_t)n1 * 3 + 2], part1 * sDirz[r0 + 8]);
    }
}

// ---------------- launch ----------------
extern "C" void kernel_launch(void* const* d_in, const int* in_sizes, int n_in,
                              void* d_out, int out_size) {
    const float* x   = (const float*)d_in[0];
    const float* h   = (const float*)d_in[1];
    const int*   ei  = (const int*)d_in[2];
    const float* pw1 = (const float*)d_in[3];
    const float* pb1 = (const float*)d_in[4];
    const float* pw2 = (const float*)d_in[5];
    const float* pb2 = (const float*)d_in[6];
    const float* pxw = (const float*)d_in[7];
    const float* hw1 = (const float*)d_in[8];
    const float* hb1 = (const float*)d_in[9];
    const float* hw2 = (const float*)d_in[10];
    const float* hb2 = (const float*)d_in[11];

    float* out   = (float*)d_out;
    float* out_x = out;
    float* out_h = out + (size_t)BN * 3;

    const int GSMEM = 2 * 10240 * (int)sizeof(float);                  // 81920 B
    const int FSMEM = (10240 + 128 * 136) * (int)sizeof(float);        // 110592 B
    const int EDGE_SMEM = (64 * 72 + EPB * 36) * (int)sizeof(float);   // 36864 B
    cudaFuncSetAttribute(gemm_p, cudaFuncAttributeMaxDynamicSharedMemorySize, GSMEM);
    cudaFuncSetAttribute(gemm_fused, cudaFuncAttributeMaxDynamicSharedMemorySize, FSMEM);
    cudaFuncSetAttribute(edge_kernel, cudaFuncAttributeMaxDynamicSharedMemorySize, EDGE_SMEM);

    prep_kernel<<<256, 256>>>(pw1, hw1, hw2, pw2);
    gemm_p<<<BN / 128, 256, GSMEM>>>(h);
    edge_kernel<<<NE / EPB, 256, EDGE_SMEM>>>(x, ei, pw1, pb1, pb2, pxw);
    gemm_fused<<<BN / 128 + 256, 256, FSMEM>>>(h, hb1, hb2, out_h, x, out_x);
}

// round 9
// speedup vs baseline: 1.1595x; 1.0189x over previous
#include <cuda_runtime.h>
#include <math.h>
#include <stdint.h>

#define BN   65536
#define NPB  16384
#define NE   262144
#define EPB  128

__device__ __align__(16) float g_P [(size_t)BN * 128];
__device__ __align__(16) float g_dh[(size_t)BN * 64];
__device__ __align__(16) float g_dx[(size_t)BN * 3];
__device__ __align__(16) float g_Bp[14 * 128 * 40];
__device__ __align__(16) float g_W2p[64 * 72];

__device__ __forceinline__ float silu_f(float v) {
    return v * (1.0f / (1.0f + __expf(-v)));
}
__device__ __forceinline__ uint32_t f2tf32(float f) {   // prep-time only
    uint32_t r;
    asm("cvt.rna.tf32.f32 %0, %1;" : "=r"(r) : "f"(f));
    return r;
}
__device__ __forceinline__ void mma_tf32(float* c, const uint32_t* a, const uint32_t* b) {
    asm volatile("mma.sync.aligned.m16n8k8.row.col.f32.tf32.tf32.f32 "
        "{%0,%1,%2,%3}, {%4,%5,%6,%7}, {%8,%9}, {%0,%1,%2,%3};"
        : "+f"(c[0]), "+f"(c[1]), "+f"(c[2]), "+f"(c[3])
        : "r"(a[0]), "r"(a[1]), "r"(a[2]), "r"(a[3]), "r"(b[0]), "r"(b[1]));
}
__device__ __forceinline__ void red_add_v2(float* p, float a, float b) {
    asm volatile("red.global.add.v2.f32 [%0], {%1,%2};"
                 :: "l"(p), "f"(a), "f"(b) : "memory");
}
__device__ __forceinline__ void cp_async16(uint32_t dst, const void* src) {
    asm volatile("cp.async.cg.shared.global [%0], [%1], 16;" :: "r"(dst), "l"(src));
}

__global__ void prep_kernel(const float* __restrict__ pw1,
                            const float* __restrict__ hw1,
                            const float* __restrict__ hw2,
                            const float* __restrict__ pw2)
{
    const int stride = gridDim.x * blockDim.x;
    const int idx0 = blockIdx.x * blockDim.x + threadIdx.x;
    {
        float4 z = make_float4(0.f, 0.f, 0.f, 0.f);
        const size_t n1 = (size_t)BN * 16;
        const size_t n2 = (size_t)BN * 3 / 4;
        const size_t total = n1 + n2;
        for (size_t i = idx0; i < total; i += stride) {
            if (i < n1) ((float4*)g_dh)[i] = z;
            else        ((float4*)g_dx)[i - n1] = z;
        }
    }
    for (int i = idx0; i < 14 * 128 * 40; i += stride) {
        const int w = i % 40, n = (i / 40) & 127, c = i / (40 * 128);
        float v = 0.f;
        if (w < 32) {
            const int g = w >> 3, s = w & 7;
            const int k8 = (s >> 1) + ((s & 1) << 2);
            if (c < 4) {
                const int k = c * 32 + g * 8 + k8;
                v = (n < 64) ? pw1[k * 64 + n] : pw1[(128 + k) * 64 + (n - 64)];
            } else if (c < 10) {
                const int k = (c - 4) * 32 + g * 8 + k8;
                v = hw1[k * 128 + n];
            } else {
                const int k = (c - 10) * 32 + g * 8 + k8;
                v = hw2[k * 128 + n];
            }
            v = __uint_as_float(f2tf32(v));
        }
        g_Bp[i] = v;
    }
    for (int i = idx0; i < 64 * 72; i += stride) {
        const int w = i % 72, n = i / 72;
        float v = 0.f;
        if (w < 64) {
            const int g = w >> 3, s = w & 7;
            const int k = g * 8 + (s >> 1) + ((s & 1) << 2);
            v = __uint_as_float(f2tf32(pw2[k * 64 + n]));
        }
        g_W2p[i] = v;
    }
}

// ============ gemm_p: CTA 128x128, warp 32x64, double-buffered ==============
__global__ __launch_bounds__(256, 2) void gemm_p(const float* __restrict__ A)
{
    extern __shared__ float sm[];
    const int BUFW = 10240;
    const int tid  = threadIdx.x;
    const int lane = tid & 31, warp = tid >> 5;
    const int wm = warp & 3, wn = warp >> 2;
    const int gq = lane >> 2, tq = lane & 3;
    const int m0 = blockIdx.x * 128;
    const uint32_t smem_u32 = (uint32_t)__cvta_generic_to_shared(sm);

    float acc[2][8][4];
#pragma unroll
    for (int i = 0; i < 2; i++)
#pragma unroll
        for (int j = 0; j < 8; j++)
#pragma unroll
            for (int q = 0; q < 4; q++) acc[i][j][q] = 0.f;

    float4 ra[4];
    const int am = tid >> 1;
    const int ah = (tid & 1) * 16;

    auto ldgA = [&](int k0) {
        const float* src = A + (size_t)(m0 + am) * 128 + k0 + ah;
        ra[0] = *(const float4*)(src);
        ra[1] = *(const float4*)(src + 4);
        ra[2] = *(const float4*)(src + 8);
        ra[3] = *(const float4*)(src + 12);
    };
    auto stsA = [&](int p) {   // raw fp32 bits -> HW truncates to tf32
        float* bA = sm + p * BUFW;
#pragma unroll
        for (int pg = 0; pg < 2; pg++) {
            const float4 u = ra[pg * 2], v = ra[pg * 2 + 1];
            *(float4*)&bA[am * 40 + ah + pg * 8]     = make_float4(u.x, v.x, u.y, v.y);
            *(float4*)&bA[am * 40 + ah + pg * 8 + 4] = make_float4(u.z, v.z, u.w, v.w);
        }
    };
    auto cpB = [&](int chunk, int p) {
        const float* src = g_Bp + (size_t)chunk * 5120;
        const uint32_t dst = smem_u32 + (p * BUFW + 5120) * 4;
#pragma unroll
        for (int it = 0; it < 5; it++) {
            const int q = tid + it * 256;
            cp_async16(dst + q * 16, src + q * 4);
        }
        asm volatile("cp.async.commit_group;" ::: "memory");
    };
    auto compute = [&](int p) {
        const uint32_t* bA = (const uint32_t*)(sm + p * BUFW);
        const uint32_t* bB = (const uint32_t*)(sm + p * BUFW + 5120);
#pragma unroll
        for (int ks = 0; ks < 4; ks++) {
            uint32_t af[2][4], bf[8][2];
#pragma unroll
            for (int i = 0; i < 2; i++) {
                const int r = wm * 32 + i * 16 + gq;
                const uint2 lo = *(const uint2*)&bA[r * 40 + ks * 8 + 2 * tq];
                const uint2 hi = *(const uint2*)&bA[(r + 8) * 40 + ks * 8 + 2 * tq];
                af[i][0] = lo.x; af[i][1] = hi.x; af[i][2] = lo.y; af[i][3] = hi.y;
            }
#pragma unroll
            for (int j = 0; j < 8; j++) {
                const int c = wn * 64 + j * 8 + gq;
                const uint2 b = *(const uint2*)&bB[c * 40 + ks * 8 + 2 * tq];
                bf[j][0] = b.x; bf[j][1] = b.y;
            }
#pragma unroll
            for (int i = 0; i < 2; i++)
#pragma unroll
                for (int j = 0; j < 8; j++)
                    mma_tf32(acc[i][j], af[i], bf[j]);
        }
    };

    ldgA(0); cpB(0, 0); stsA(0);
    asm volatile("cp.async.wait_group 0;" ::: "memory");
    __syncthreads();
    for (int c = 0; c < 4; c++) {
        if (c + 1 < 4) { ldgA((c + 1) * 32); cpB(c + 1, (c + 1) & 1); }
        compute(c & 1);
        if (c + 1 < 4) stsA((c + 1) & 1);
        asm volatile("cp.async.wait_group 0;" ::: "memory");
        __syncthreads();
    }

#pragma unroll
    for (int i = 0; i < 2; i++)
#pragma unroll
        for (int h2 = 0; h2 < 2; h2++) {
            const int r = m0 + wm * 32 + i * 16 + gq + h2 * 8;
#pragma unroll
            for (int j = 0; j < 8; j++) {
                const int c = wn * 64 + j * 8 + tq * 2;
                *(float2*)(g_P + (size_t)r * 128 + c) =
                    make_float2(acc[i][j][h2 * 2 + 0], acc[i][j][h2 * 2 + 1]);
            }
        }
}

// ===== fused node MLP, 2 CTAs/SM via smem overlay ===========================
// layout (words): B0 @0, B1 @5120, A_p @10240+p*5120, tT overlays @10240
__global__ __launch_bounds__(256, 2) void gemm_fused(
    const float* __restrict__ A,
    const float* __restrict__ b1,
    const float* __restrict__ b2,
    float* __restrict__ OutH,
    const float* __restrict__ X,
    float* __restrict__ OutX)
{
    extern __shared__ float sm[];
    __shared__ float sB1s[128], sB2s[128];

    if (blockIdx.x >= 512) {
        const int t0 = (blockIdx.x - 512) * 256 + threadIdx.x;
        for (int i = t0; i < BN * 3; i += 256 * 256)
            OutX[i] = X[i] + g_dx[i];
        return;
    }

    const int tid  = threadIdx.x;
    const int lane = tid & 31, warp = tid >> 5;
    const int wm = warp & 3, wn = warp >> 2;
    const int gq = lane >> 2, tq = lane & 3;
    const int m0 = blockIdx.x * 128;
    const uint32_t smem_u32 = (uint32_t)__cvta_generic_to_shared(sm);
    uint32_t* tT = (uint32_t*)(sm + 10240);   // [128][136], overlays A slots

    if (tid < 128) sB1s[tid] = b1[tid];
    else           sB2s[tid - 128] = b2[tid - 128];

    float4 ra[4];
    const int am = tid >> 1;
    const int ah = (tid & 1) * 16;

    auto ldgA = [&](int k0) {
        const int f = k0 + ah;
        const float* src = (f < 128) ? (A + (size_t)(m0 + am) * 128 + f)
                                     : (g_dh + (size_t)(m0 + am) * 64 + (f - 128));
        ra[0] = *(const float4*)(src);
        ra[1] = *(const float4*)(src + 4);
        ra[2] = *(const float4*)(src + 8);
        ra[3] = *(const float4*)(src + 12);
    };
    auto stsA = [&](int p) {   // raw fp32 bits
        float* bA = sm + 10240 + p * 5120;
#pragma unroll
        for (int pg = 0; pg < 2; pg++) {
            const float4 u = ra[pg * 2], v = ra[pg * 2 + 1];
            *(float4*)&bA[am * 40 + ah + pg * 8]     = make_float4(u.x, v.x, u.y, v.y);
            *(float4*)&bA[am * 40 + ah + pg * 8 + 4] = make_float4(u.z, v.z, u.w, v.w);
        }
    };
    auto cpB = [&](int chunk, int p) {
        const float* src = g_Bp + (size_t)chunk * 5120;
        const uint32_t dst = smem_u32 + (p * 5120) * 4;
#pragma unroll
        for (int it = 0; it < 5; it++) {
            const int q = tid + it * 256;
            cp_async16(dst + q * 16, src + q * 4);
        }
        asm volatile("cp.async.commit_group;" ::: "memory");
    };

    const int sl0 = ((2 * tq) & 3) * 2 + ((2 * tq) >> 2);
    const int sl1 = ((2 * tq + 1) & 3) * 2 + ((2 * tq + 1) >> 2);

    // ---------------- phase 1: t = silu([h|dh]@W1 + b1) ----------------
    {
        float acc[2][8][4];
#pragma unroll
        for (int i = 0; i < 2; i++)
#pragma unroll
            for (int j = 0; j < 8; j++)
#pragma unroll
                for (int q = 0; q < 4; q++) acc[i][j][q] = 0.f;

        auto compute = [&](int p) {
            const uint32_t* bA = (const uint32_t*)(sm + 10240 + p * 5120);
            const uint32_t* bB = (const uint32_t*)(sm + p * 5120);
#pragma unroll
            for (int ks = 0; ks < 4; ks++) {
                uint32_t af[2][4], bf[8][2];
#pragma unroll
                for (int i = 0; i < 2; i++) {
                    const int r = wm * 32 + i * 16 + gq;
                    const uint2 lo = *(const uint2*)&bA[r * 40 + ks * 8 + 2 * tq];
                    const uint2 hi = *(const uint2*)&bA[(r + 8) * 40 + ks * 8 + 2 * tq];
                    af[i][0] = lo.x; af[i][1] = hi.x; af[i][2] = lo.y; af[i][3] = hi.y;
                }
#pragma unroll
                for (int j = 0; j < 8; j++) {
                    const int c = wn * 64 + j * 8 + gq;
                    const uint2 b = *(const uint2*)&bB[c * 40 + ks * 8 + 2 * tq];
                    bf[j][0] = b.x; bf[j][1] = b.y;
                }
#pragma unroll
                for (int i = 0; i < 2; i++)
#pragma unroll
                    for (int j = 0; j < 8; j++)
                        mma_tf32(acc[i][j], af[i], bf[j]);
            }
        };

        ldgA(0); cpB(4, 0); stsA(0);
        asm volatile("cp.async.wait_group 0;" ::: "memory");
        __syncthreads();
        for (int c = 0; c < 6; c++) {
            if (c + 1 < 6) { ldgA((c + 1) * 32); cpB(5 + c, (c + 1) & 1); }
            compute(c & 1);
            if (c + 1 < 6) stsA((c + 1) & 1);
            asm volatile("cp.async.wait_group 0;" ::: "memory");
            __syncthreads();
        }

        // epilogue 1: silu(+b1) -> tT (raw fp32 bits)
#pragma unroll
        for (int i = 0; i < 2; i++)
#pragma unroll
            for (int h2 = 0; h2 < 2; h2++) {
                const int rl = wm * 32 + i * 16 + gq + h2 * 8;
#pragma unroll
                for (int j = 0; j < 8; j++) {
                    const int c = wn * 64 + j * 8 + tq * 2;
                    const float v0 = silu_f(acc[i][j][h2 * 2 + 0] + sB1s[c]);
                    const float v1 = silu_f(acc[i][j][h2 * 2 + 1] + sB1s[c + 1]);
                    uint32_t* d = &tT[rl * 136 + (c >> 3) * 8];
                    d[sl0] = __float_as_uint(v0);
                    d[sl1] = __float_as_uint(v1);
                }
            }
    }
    __syncthreads();

    // ---------------- phase 2: out = h + t@W2 + b2 ----------------
    {
        float acc[2][8][4];
#pragma unroll
        for (int i = 0; i < 2; i++)
#pragma unroll
            for (int j = 0; j < 8; j++)
#pragma unroll
                for (int q = 0; q < 4; q++) acc[i][j][q] = 0.f;

        cpB(10, 0);
        asm volatile("cp.async.wait_group 0;" ::: "memory");
        __syncthreads();
        for (int kc = 0; kc < 4; kc++) {
            if (kc + 1 < 4) cpB(11 + kc, (kc + 1) & 1);
            const uint32_t* bB = (const uint32_t*)(sm + (kc & 1) * 5120);
#pragma unroll
            for (int ks = 0; ks < 4; ks++) {
                const int kg = kc * 4 + ks;
                uint32_t af[2][4], bf[8][2];
#pragma unroll
                for (int i = 0; i < 2; i++) {
                    const int r = wm * 32 + i * 16 + gq;
                    const uint2 lo = *(const uint2*)&tT[r * 136 + kg * 8 + 2 * tq];
                    const uint2 hi = *(const uint2*)&tT[(r + 8) * 136 + kg * 8 + 2 * tq];
                    af[i][0] = lo.x; af[i][1] = hi.x; af[i][2] = lo.y; af[i][3] = hi.y;
                }
#pragma unroll
                for (int j = 0; j < 8; j++) {
                    const int c = wn * 64 + j * 8 + gq;
                    const uint2 b = *(const uint2*)&bB[c * 40 + ks * 8 + 2 * tq];
                    bf[j][0] = b.x; bf[j][1] = b.y;
                }
#pragma unroll
                for (int i = 0; i < 2; i++)
#pragma unroll
                    for (int j = 0; j < 8; j++)
                        mma_tf32(acc[i][j], af[i], bf[j]);
            }
            asm volatile("cp.async.wait_group 0;" ::: "memory");
            __syncthreads();
        }

#pragma unroll
        for (int i = 0; i < 2; i++)
#pragma unroll
            for (int h2 = 0; h2 < 2; h2++) {
                const int r = m0 + wm * 32 + i * 16 + gq + h2 * 8;
#pragma unroll
                for (int j = 0; j < 8; j++) {
                    const int c = wn * 64 + j * 8 + tq * 2;
                    const size_t base = (size_t)r * 128 + c;
                    const float2 hh = *(const float2*)(A + base);
                    const float v0 = acc[i][j][h2 * 2 + 0] + sB2s[c] + hh.x;
                    const float v1 = acc[i][j][h2 * 2 + 1] + sB2s[c + 1] + hh.y;
                    *(float2*)(OutH + base) = make_float2(v0, v1);
                }
            }
    }
}

// -------- edge kernel: 128 edges/block, 256 threads, 4 CTAs/SM, K-split -----
__global__ __launch_bounds__(256, 4) void edge_kernel(
    const float* __restrict__ x,
    const int*   __restrict__ edges,
    const float* __restrict__ W1,
    const float* __restrict__ b1,
    const float* __restrict__ b2,
    const float* __restrict__ pxw)
{
    extern __shared__ float dyn[];
    float* sW2 = dyn;
    float* sM  = dyn + 64 * 72;
    const uint32_t* sW2u = (const uint32_t*)sW2;
    const uint32_t* sMu  = (const uint32_t*)sM;

    __shared__ int   sSrc[EPB], sDst[EPB];
    __shared__ float sD2[EPB];
    __shared__ float sDirx[EPB], sDiry[EPB], sDirz[EPB];
    __shared__ float sB1[64], sB2[64], sPx[64], sW1r[64];

    const int tid  = threadIdx.x;
    const int lane = tid & 31, warp = tid >> 5;
    const int gq = lane >> 2, tq = lane & 3;
    const int e0 = blockIdx.x * EPB;

    if (tid < EPB) {
        const int eg = e0 + tid;
        const int b  = eg >> 16;
        const int2 sd = ((const int2*)edges)[eg];
        const int gi = b * NPB + sd.x;
        const int gj = b * NPB + sd.y;
        sSrc[tid] = gi; sDst[tid] = gj;
        const float xi0 = x[(size_t)gi * 3 + 0], xi1 = x[(size_t)gi * 3 + 1], xi2 = x[(size_t)gi * 3 + 2];
        const float xj0 = x[(size_t)gj * 3 + 0], xj1 = x[(size_t)gj * 3 + 1], xj2 = x[(size_t)gj * 3 + 2];
        const float d0 = xi0 - xj0, d1 = xi1 - xj1, d2c = xi2 - xj2;
        float d2 = d0 * d0 + d1 * d1 + d2c * d2c;
        d2 = fmaxf(d2, 1e-12f);
        sD2[tid] = d2;
        const float inv = 1.0f / (sqrtf(d2) + 1e-8f);
        sDirx[tid] = d0 * inv; sDiry[tid] = d1 * inv; sDirz[tid] = d2c * inv;
    }
    if (tid >= 128 && tid < 192) {
        const int t = tid - 128;
        sB1[t] = b1[t];
        sB2[t] = b2[t];
        sPx[t] = pxw[t];
        sW1r[t] = W1[256 * 64 + t];
    }
#pragma unroll
    for (int it = 0; it < 5; it++) {
        const int q = tid + it * 256;
        if (q < 1152) *(float4*)&sW2[q * 4] = *(const float4*)&g_W2p[q * 4];
    }
    __syncthreads();

    float acc[8][4];
#pragma unroll
    for (int j = 0; j < 8; j++)
#pragma unroll
        for (int q = 0; q < 4; q++) acc[j][q] = 0.f;

#pragma unroll
    for (int h = 0; h < 2; h++) {
#pragma unroll
        for (int it = 0; it < 4; ++it) {
            const int idx = it * 256 + tid;
            const int e = idx >> 3, qp = idx & 7;
            const int k = h * 32 + qp * 4;
            const float4 a = *(const float4*)(g_P + (size_t)sSrc[e] * 128 + k);
            const float4 b = *(const float4*)(g_P + (size_t)sDst[e] * 128 + 64 + k);
            const float4 wv = *(const float4*)&sW1r[k];
            const float4 bv = *(const float4*)&sB1[k];
            const float d2 = sD2[e];
            float* dst = &sM[e * 36 + (qp >> 1) * 8 + (qp & 1)];
            dst[0] = silu_f(a.x + b.x + d2 * wv.x + bv.x);
            dst[2] = silu_f(a.y + b.y + d2 * wv.y + bv.y);
            dst[4] = silu_f(a.z + b.z + d2 * wv.z + bv.z);
            dst[6] = silu_f(a.w + b.w + d2 * wv.w + bv.w);
        }
        __syncthreads();

#pragma unroll
        for (int ksl = 0; ksl < 4; ksl++) {
            const int ks = h * 4 + ksl;
            uint32_t af[4], bf[2];
            const int r = warp * 16 + gq;
            const uint2 lo = *(const uint2*)&sMu[r * 36 + ksl * 8 + 2 * tq];
            const uint2 hi = *(const uint2*)&sMu[(r + 8) * 36 + ksl * 8 + 2 * tq];
            af[0] = lo.x; af[1] = hi.x; af[2] = lo.y; af[3] = hi.y;
#pragma unroll
            for (int j = 0; j < 8; j++) {
                const int c = j * 8 + gq;
                const uint2 b = *(const uint2*)&sW2u[c * 72 + ks * 8 + 2 * tq];
                bf[0] = b.x; bf[1] = b.y;
                mma_tf32(acc[j], af, bf);
            }
        }
        if (h == 0) __syncthreads();
    }

    const int r0 = warp * 16 + gq;
    const int n0 = sSrc[r0], n1 = sSrc[r0 + 8];
    float part0 = 0.f, part1 = 0.f;
#pragma unroll
    for (int j = 0; j < 8; j++) {
        const int c = j * 8 + tq * 2;
        const float bb0 = sB2[c], bb1 = sB2[c + 1];
        const float px0 = sPx[c], px1 = sPx[c + 1];
        const float v0 = silu_f(acc[j][0] + bb0);
        const float v1 = silu_f(acc[j][1] + bb1);
        const float v2 = silu_f(acc[j][2] + bb0);
        const float v3 = silu_f(acc[j][3] + bb1);
        part0 += v0 * px0 + v1 * px1;
        part1 += v2 * px0 + v3 * px1;
        red_add_v2(g_dh + (size_t)n0 * 64 + c, v0, v1);
        red_add_v2(g_dh + (size_t)n1 * 64 + c, v2, v3);
    }
    part0 += __shfl_xor_sync(0xffffffffu, part0, 1);
    part0 += __shfl_xor_sync(0xffffffffu, part0, 2);
    part1 += __shfl_xor_sync(0xffffffffu, part1, 1);
    part1 += __shfl_xor_sync(0xffffffffu, part1, 2);
    if (tq == 0) {
        atomicAdd(&g_dx[(size_t)n0 * 3 + 0], part0 * sDirx[r0]);
        atomicAdd(&g_dx[(size_t)n0 * 3 + 1], part0 * sDiry[r0]);
        atomicAdd(&g_dx[(size_t)n0 * 3 + 2], part0 * sDirz[r0]);
        atomicAdd(&g_dx[(size_t)n1 * 3 + 0], part1 * sDirx[r0 + 8]);
        atomicAdd(&g_dx[(size_t)n1 * 3 + 1], part1 * sDiry[r0 + 8]);
        atomicAdd(&g_dx[(size_t)n1 * 3 + 2], part1 * sDirz[r0 + 8]);
    }
}

// ---------------- launch ----------------
extern "C" void kernel_launch(void* const* d_in, const int* in_sizes, int n_in,
                              void* d_out, int out_size) {
    const float* x   = (const float*)d_in[0];
    const float* h   = (const float*)d_in[1];
    const int*   ei  = (const int*)d_in[2];
    const float* pw1 = (const float*)d_in[3];
    const float* pb1 = (const float*)d_in[4];
    const float* pw2 = (const float*)d_in[5];
    const float* pb2 = (const float*)d_in[6];
    const float* pxw = (const float*)d_in[7];
    const float* hw1 = (const float*)d_in[8];
    const float* hb1 = (const float*)d_in[9];
    const float* hw2 = (const float*)d_in[10];
    const float* hb2 = (const float*)d_in[11];

    float* out   = (float*)d_out;
    float* out_x = out;
    float* out_h = out + (size_t)BN * 3;

    const int GSMEM = 2 * 10240 * (int)sizeof(float);                  // 81920 B
    const int FSMEM = (10240 + 128 * 136) * (int)sizeof(float);        // 110592 B
    const int EDGE_SMEM = (64 * 72 + EPB * 36) * (int)sizeof(float);   // 36864 B
    cudaFuncSetAttribute(gemm_p, cudaFuncAttributeMaxDynamicSharedMemorySize, GSMEM);
    cudaFuncSetAttribute(gemm_fused, cudaFuncAttributeMaxDynamicSharedMemorySize, FSMEM);
    cudaFuncSetAttribute(edge_kernel, cudaFuncAttributeMaxDynamicSharedMemorySize, EDGE_SMEM);

    prep_kernel<<<256, 256>>>(pw1, hw1, hw2, pw2);
    gemm_p<<<BN / 128, 256, GSMEM>>>(h);
    edge_kernel<<<NE / EPB, 256, EDGE_SMEM>>>(x, ei, pw1, pb1, pb2, pxw);
    gemm_fused<<<BN / 128 + 256, 256, FSMEM>>>(h, hb1, hb2, out_h, x, out_x);
}

// round 10
// speedup vs baseline: 1.1838x; 1.0210x over previous
#include <cuda_runtime.h>
#include <math.h>
#include <stdint.h>

#define BN   65536
#define NPB  16384
#define NE   262144
#define EPB  128

__device__ __align__(16) float g_P [(size_t)BN * 128];
__device__ __align__(16) float g_dh[(size_t)BN * 64];
__device__ __align__(16) float g_dx[(size_t)BN * 3];
__device__ __align__(16) float g_Bp[14 * 128 * 40];
__device__ __align__(16) float g_W2p[64 * 72];

__device__ __forceinline__ float silu_f(float v) {
    return v * (1.0f / (1.0f + __expf(-v)));
}
__device__ __forceinline__ uint32_t f2tf32(float f) {   // prep-time only
    uint32_t r;
    asm("cvt.rna.tf32.f32 %0, %1;" : "=r"(r) : "f"(f));
    return r;
}
__device__ __forceinline__ void mma_tf32(float* c, const uint32_t* a, const uint32_t* b) {
    asm volatile("mma.sync.aligned.m16n8k8.row.col.f32.tf32.tf32.f32 "
        "{%0,%1,%2,%3}, {%4,%5,%6,%7}, {%8,%9}, {%0,%1,%2,%3};"
        : "+f"(c[0]), "+f"(c[1]), "+f"(c[2]), "+f"(c[3])
        : "r"(a[0]), "r"(a[1]), "r"(a[2]), "r"(a[3]), "r"(b[0]), "r"(b[1]));
}
__device__ __forceinline__ void red_add_v2(float* p, float a, float b) {
    asm volatile("red.global.add.v2.f32 [%0], {%1,%2};"
                 :: "l"(p), "f"(a), "f"(b) : "memory");
}
__device__ __forceinline__ void cp_async16(uint32_t dst, const void* src) {
    asm volatile("cp.async.cg.shared.global [%0], [%1], 16;" :: "r"(dst), "l"(src));
}

// ---------------- prep: weights only (zeroing moved to gemm_p tail) --------
__global__ void prep_kernel(const float* __restrict__ pw1,
                            const float* __restrict__ hw1,
                            const float* __restrict__ hw2,
                            const float* __restrict__ pw2)
{
    const int stride = gridDim.x * blockDim.x;
    const int idx0 = blockIdx.x * blockDim.x + threadIdx.x;
    for (int i = idx0; i < 14 * 128 * 40; i += stride) {
        const int w = i % 40, n = (i / 40) & 127, c = i / (40 * 128);
        float v = 0.f;
        if (w < 32) {
            const int g = w >> 3, s = w & 7;
            const int k8 = (s >> 1) + ((s & 1) << 2);
            if (c < 4) {
                const int k = c * 32 + g * 8 + k8;
                v = (n < 64) ? pw1[k * 64 + n] : pw1[(128 + k) * 64 + (n - 64)];
            } else if (c < 10) {
                const int k = (c - 4) * 32 + g * 8 + k8;
                v = hw1[k * 128 + n];
            } else {
                const int k = (c - 10) * 32 + g * 8 + k8;
                v = hw2[k * 128 + n];
            }
            v = __uint_as_float(f2tf32(v));
        }
        g_Bp[i] = v;
    }
    for (int i = idx0; i < 64 * 72; i += stride) {
        const int w = i % 72, n = i / 72;
        float v = 0.f;
        if (w < 64) {
            const int g = w >> 3, s = w & 7;
            const int k = g * 8 + (s >> 1) + ((s & 1) << 2);
            v = __uint_as_float(f2tf32(pw2[k * 64 + n]));
        }
        g_W2p[i] = v;
    }
}

// ============ gemm_p: CTA 128x128, warp 32x64 + zero tail ===================
__global__ __launch_bounds__(256, 2) void gemm_p(const float* __restrict__ A)
{
    extern __shared__ float sm[];
    const int BUFW = 10240;

    if (blockIdx.x >= 512) {          // zero g_dh / g_dx (overlaps P compute)
        const int t0 = (blockIdx.x - 512) * 256 + threadIdx.x;
        float4 z = make_float4(0.f, 0.f, 0.f, 0.f);
        const int n1 = BN * 16;
        const int n2 = BN * 3 / 4;
        for (int i = t0; i < n1 + n2; i += 256 * 256) {
            if (i < n1) ((float4*)g_dh)[i] = z;
            else        ((float4*)g_dx)[i - n1] = z;
        }
        return;
    }

    const int tid  = threadIdx.x;
    const int lane = tid & 31, warp = tid >> 5;
    const int wm = warp & 3, wn = warp >> 2;
    const int gq = lane >> 2, tq = lane & 3;
    const int m0 = blockIdx.x * 128;
    const uint32_t smem_u32 = (uint32_t)__cvta_generic_to_shared(sm);

    float acc[2][8][4];
#pragma unroll
    for (int i = 0; i < 2; i++)
#pragma unroll
        for (int j = 0; j < 8; j++)
#pragma unroll
            for (int q = 0; q < 4; q++) acc[i][j][q] = 0.f;

    float4 ra[4];
    const int am = tid >> 1;
    const int ah = (tid & 1) * 16;

    auto ldgA = [&](int k0) {
        const float* src = A + (size_t)(m0 + am) * 128 + k0 + ah;
        ra[0] = *(const float4*)(src);
        ra[1] = *(const float4*)(src + 4);
        ra[2] = *(const float4*)(src + 8);
        ra[3] = *(const float4*)(src + 12);
    };
    auto stsA = [&](int p) {
        float* bA = sm + p * BUFW;
#pragma unroll
        for (int pg = 0; pg < 2; pg++) {
            const float4 u = ra[pg * 2], v = ra[pg * 2 + 1];
            *(float4*)&bA[am * 40 + ah + pg * 8]     = make_float4(u.x, v.x, u.y, v.y);
            *(float4*)&bA[am * 40 + ah + pg * 8 + 4] = make_float4(u.z, v.z, u.w, v.w);
        }
    };
    auto cpB = [&](int chunk, int p) {
        const float* src = g_Bp + (size_t)chunk * 5120;
        const uint32_t dst = smem_u32 + (p * BUFW + 5120) * 4;
#pragma unroll
        for (int it = 0; it < 5; it++) {
            const int q = tid + it * 256;
            cp_async16(dst + q * 16, src + q * 4);
        }
        asm volatile("cp.async.commit_group;" ::: "memory");
    };
    auto compute = [&](int p) {
        const uint32_t* bA = (const uint32_t*)(sm + p * BUFW);
        const uint32_t* bB = (const uint32_t*)(sm + p * BUFW + 5120);
#pragma unroll
        for (int ks = 0; ks < 4; ks++) {
            uint32_t af[2][4], bf[8][2];
#pragma unroll
            for (int i = 0; i < 2; i++) {
                const int r = wm * 32 + i * 16 + gq;
                const uint2 lo = *(const uint2*)&bA[r * 40 + ks * 8 + 2 * tq];
                const uint2 hi = *(const uint2*)&bA[(r + 8) * 40 + ks * 8 + 2 * tq];
                af[i][0] = lo.x; af[i][1] = hi.x; af[i][2] = lo.y; af[i][3] = hi.y;
            }
#pragma unroll
            for (int j = 0; j < 8; j++) {
                const int c = wn * 64 + j * 8 + gq;
                const uint2 b = *(const uint2*)&bB[c * 40 + ks * 8 + 2 * tq];
                bf[j][0] = b.x; bf[j][1] = b.y;
            }
#pragma unroll
            for (int i = 0; i < 2; i++)
#pragma unroll
                for (int j = 0; j < 8; j++)
                    mma_tf32(acc[i][j], af[i], bf[j]);
        }
    };

    ldgA(0); cpB(0, 0); stsA(0);
    asm volatile("cp.async.wait_group 0;" ::: "memory");
    __syncthreads();
    for (int c = 0; c < 4; c++) {
        if (c + 1 < 4) { ldgA((c + 1) * 32); cpB(c + 1, (c + 1) & 1); }
        compute(c & 1);
        if (c + 1 < 4) {
            stsA((c + 1) & 1);
            asm volatile("cp.async.wait_group 0;" ::: "memory");
            __syncthreads();
        }
    }

#pragma unroll
    for (int i = 0; i < 2; i++)
#pragma unroll
        for (int h2 = 0; h2 < 2; h2++) {
            const int r = m0 + wm * 32 + i * 16 + gq + h2 * 8;
#pragma unroll
            for (int j = 0; j < 8; j++) {
                const int c = wn * 64 + j * 8 + tq * 2;
                *(float2*)(g_P + (size_t)r * 128 + c) =
                    make_float2(acc[i][j][h2 * 2 + 0], acc[i][j][h2 * 2 + 1]);
            }
        }
}

// ===== fused node MLP, 2 CTAs/SM, cross-phase prefetched ====================
// layout (words): B0 @0, B1 @5120, A_p @10240+p*5120, tT overlays @10240
__global__ __launch_bounds__(256, 2) void gemm_fused(
    const float* __restrict__ A,
    const float* __restrict__ b1,
    const float* __restrict__ b2,
    float* __restrict__ OutH,
    const float* __restrict__ X,
    float* __restrict__ OutX)
{
    extern __shared__ float sm[];
    __shared__ float sB1s[128], sB2s[128];

    if (blockIdx.x >= 512) {
        const int t0 = (blockIdx.x - 512) * 256 + threadIdx.x;
        for (int i = t0; i < BN * 3; i += 256 * 256)
            OutX[i] = X[i] + g_dx[i];
        return;
    }

    const int tid  = threadIdx.x;
    const int lane = tid & 31, warp = tid >> 5;
    const int wm = warp & 3, wn = warp >> 2;
    const int gq = lane >> 2, tq = lane & 3;
    const int m0 = blockIdx.x * 128;
    const uint32_t smem_u32 = (uint32_t)__cvta_generic_to_shared(sm);
    uint32_t* tT = (uint32_t*)(sm + 10240);   // [128][136], overlays A slots

    if (tid < 128) sB1s[tid] = b1[tid];
    else           sB2s[tid - 128] = b2[tid - 128];

    float4 ra[4];
    const int am = tid >> 1;
    const int ah = (tid & 1) * 16;

    auto ldgA = [&](int k0) {
        const int f = k0 + ah;
        const float* src = (f < 128) ? (A + (size_t)(m0 + am) * 128 + f)
                                     : (g_dh + (size_t)(m0 + am) * 64 + (f - 128));
        ra[0] = *(const float4*)(src);
        ra[1] = *(const float4*)(src + 4);
        ra[2] = *(const float4*)(src + 8);
        ra[3] = *(const float4*)(src + 12);
    };
    auto stsA = [&](int p) {
        float* bA = sm + 10240 + p * 5120;
#pragma unroll
        for (int pg = 0; pg < 2; pg++) {
            const float4 u = ra[pg * 2], v = ra[pg * 2 + 1];
            *(float4*)&bA[am * 40 + ah + pg * 8]     = make_float4(u.x, v.x, u.y, v.y);
            *(float4*)&bA[am * 40 + ah + pg * 8 + 4] = make_float4(u.z, v.z, u.w, v.w);
        }
    };
    auto cpB = [&](int chunk, int p) {
        const float* src = g_Bp + (size_t)chunk * 5120;
        const uint32_t dst = smem_u32 + (p * 5120) * 4;
#pragma unroll
        for (int it = 0; it < 5; it++) {
            const int q = tid + it * 256;
            cp_async16(dst + q * 16, src + q * 4);
        }
        asm volatile("cp.async.commit_group;" ::: "memory");
    };

    const int sl0 = ((2 * tq) & 3) * 2 + ((2 * tq) >> 2);
    const int sl1 = ((2 * tq + 1) & 3) * 2 + ((2 * tq + 1) >> 2);

    // ---------------- phase 1: t = silu([h|dh]@W1 + b1) ----------------
    {
        float acc[2][8][4];
#pragma unroll
        for (int i = 0; i < 2; i++)
#pragma unroll
            for (int j = 0; j < 8; j++)
#pragma unroll
                for (int q = 0; q < 4; q++) acc[i][j][q] = 0.f;

        auto compute = [&](int p) {
            const uint32_t* bA = (const uint32_t*)(sm + 10240 + p * 5120);
            const uint32_t* bB = (const uint32_t*)(sm + p * 5120);
#pragma unroll
            for (int ks = 0; ks < 4; ks++) {
                uint32_t af[2][4], bf[8][2];
#pragma unroll
                for (int i = 0; i < 2; i++) {
                    const int r = wm * 32 + i * 16 + gq;
                    const uint2 lo = *(const uint2*)&bA[r * 40 + ks * 8 + 2 * tq];
                    const uint2 hi = *(const uint2*)&bA[(r + 8) * 40 + ks * 8 + 2 * tq];
                    af[i][0] = lo.x; af[i][1] = hi.x; af[i][2] = lo.y; af[i][3] = hi.y;
                }
#pragma unroll
                for (int j = 0; j < 8; j++) {
                    const int c = wn * 64 + j * 8 + gq;
                    const uint2 b = *(const uint2*)&bB[c * 40 + ks * 8 + 2 * tq];
                    bf[j][0] = b.x; bf[j][1] = b.y;
                }
#pragma unroll
                for (int i = 0; i < 2; i++)
#pragma unroll
                    for (int j = 0; j < 8; j++)
                        mma_tf32(acc[i][j], af[i], bf[j]);
            }
        };

        ldgA(0); cpB(4, 0); stsA(0);
        asm volatile("cp.async.wait_group 0;" ::: "memory");
        __syncthreads();
        for (int c = 0; c < 6; c++) {
            if (c + 1 < 6) { ldgA((c + 1) * 32); cpB(5 + c, (c + 1) & 1); }
            if (c == 5)    cpB(10, 0);   // prefetch phase-2 chunk into dead buf0
            compute(c & 1);
            if (c + 1 < 6) {
                stsA((c + 1) & 1);
                asm volatile("cp.async.wait_group 0;" ::: "memory");
                __syncthreads();
            } else {
                __syncthreads();          // barrier only — chunk 10 stays in flight
            }
        }

        // epilogue 1: silu(+b1) -> tT (raw fp32 bits)
#pragma unroll
        for (int i = 0; i < 2; i++)
#pragma unroll
            for (int h2 = 0; h2 < 2; h2++) {
                const int rl = wm * 32 + i * 16 + gq + h2 * 8;
#pragma unroll
                for (int j = 0; j < 8; j++) {
                    const int c = wn * 64 + j * 8 + tq * 2;
                    const float v0 = silu_f(acc[i][j][h2 * 2 + 0] + sB1s[c]);
                    const float v1 = silu_f(acc[i][j][h2 * 2 + 1] + sB1s[c + 1]);
                    uint32_t* d = &tT[rl * 136 + (c >> 3) * 8];
                    d[sl0] = __float_as_uint(v0);
                    d[sl1] = __float_as_uint(v1);
                }
            }
    }

    // ---------------- phase 2: out = h + t@W2 + b2 (2-deep pipeline) -------
    {
        float acc[2][8][4];
#pragma unroll
        for (int i = 0; i < 2; i++)
#pragma unroll
            for (int j = 0; j < 8; j++)
#pragma unroll
                for (int q = 0; q < 4; q++) acc[i][j][q] = 0.f;

        cpB(11, 1);
        asm volatile("cp.async.wait_group 1;" ::: "memory");  // chunk 10 ready
        __syncthreads();                                       // + tT visible

        for (int kc = 0; kc < 4; kc++) {
            const uint32_t* bB = (const uint32_t*)(sm + (kc & 1) * 5120);
#pragma unroll
            for (int ks = 0; ks < 4; ks++) {
                const int kg = kc * 4 + ks;
                uint32_t af[2][4], bf[8][2];
#pragma unroll
                for (int i = 0; i < 2; i++) {
                    const int r = wm * 32 + i * 16 + gq;
                    const uint2 lo = *(const uint2*)&tT[r * 136 + kg * 8 + 2 * tq];
                    const uint2 hi = *(const uint2*)&tT[(r + 8) * 136 + kg * 8 + 2 * tq];
                    af[i][0] = lo.x; af[i][1] = hi.x; af[i][2] = lo.y; af[i][3] = hi.y;
                }
#pragma unroll
                for (int j = 0; j < 8; j++) {
                    const int c = wn * 64 + j * 8 + gq;
                    const uint2 b = *(const uint2*)&bB[c * 40 + ks * 8 + 2 * tq];
                    bf[j][0] = b.x; bf[j][1] = b.y;
                }
#pragma unroll
                for (int i = 0; i < 2; i++)
#pragma unroll
                    for (int j = 0; j < 8; j++)
                        mma_tf32(acc[i][j], af[i], bf[j]);
            }
            if (kc < 3) {
                asm volatile("cp.async.wait_group 0;" ::: "memory");
                __syncthreads();
                if (kc + 2 < 4) cpB(12 + kc, kc & 1);
            }
        }

#pragma unroll
        for (int i = 0; i < 2; i++)
#pragma unroll
            for (int h2 = 0; h2 < 2; h2++) {
                const int r = m0 + wm * 32 + i * 16 + gq + h2 * 8;
#pragma unroll
                for (int j = 0; j < 8; j++) {
                    const int c = wn * 64 + j * 8 + tq * 2;
                    const size_t base = (size_t)r * 128 + c;
                    const float2 hh = *(const float2*)(A + base);
                    const float v0 = acc[i][j][h2 * 2 + 0] + sB2s[c] + hh.x;
                    const float v1 = acc[i][j][h2 * 2 + 1] + sB2s[c + 1] + hh.y;
                    *(float2*)(OutH + base) = make_float2(v0, v1);
                }
            }
    }
}

// -------- edge kernel: 128 edges/block, 256 threads, 4 CTAs/SM, K-split -----
__global__ __launch_bounds__(256, 4) void edge_kernel(
    const float* __restrict__ x,
    const int*   __restrict__ edges,
    const float* __restrict__ W1,
    const float* __restrict__ b1,
    const float* __restrict__ b2,
    const float* __restrict__ pxw)
{
    extern __shared__ float dyn[];
    float* sW2 = dyn;
    float* sM  = dyn + 64 * 72;
    const uint32_t* sW2u = (const uint32_t*)sW2;
    const uint32_t* sMu  = (const uint32_t*)sM;

    __shared__ int   sSrc[EPB], sDst[EPB];
    __shared__ float sD2[EPB];
    __shared__ float sDirx[EPB], sDiry[EPB], sDirz[EPB];
    __shared__ float sB1[64], sB2[64], sPx[64], sW1r[64];

    const int tid  = threadIdx.x;
    const int lane = tid & 31, warp = tid >> 5;
    const int gq = lane >> 2, tq = lane & 3;
    const int e0 = blockIdx.x * EPB;

    if (tid < EPB) {
        const int eg = e0 + tid;
        const int b  = eg >> 16;
        const int2 sd = ((const int2*)edges)[eg];
        const int gi = b * NPB + sd.x;
        const int gj = b * NPB + sd.y;
        sSrc[tid] = gi; sDst[tid] = gj;
        const float xi0 = x[(size_t)gi * 3 + 0], xi1 = x[(size_t)gi * 3 + 1], xi2 = x[(size_t)gi * 3 + 2];
        const float xj0 = x[(size_t)gj * 3 + 0], xj1 = x[(size_t)gj * 3 + 1], xj2 = x[(size_t)gj * 3 + 2];
        const float d0 = xi0 - xj0, d1 = xi1 - xj1, d2c = xi2 - xj2;
        float d2 = d0 * d0 + d1 * d1 + d2c * d2c;
        d2 = fmaxf(d2, 1e-12f);
        sD2[tid] = d2;
        const float inv = 1.0f / (sqrtf(d2) + 1e-8f);
        sDirx[tid] = d0 * inv; sDiry[tid] = d1 * inv; sDirz[tid] = d2c * inv;
    }
    if (tid >= 128 && tid < 192) {
        const int t = tid - 128;
        sB1[t] = b1[t];
        sB2[t] = b2[t];
        sPx[t] = pxw[t];
        sW1r[t] = W1[256 * 64 + t];
    }
#pragma unroll
    for (int it = 0; it < 5; it++) {
        const int q = tid + it * 256;
        if (q < 1152) *(float4*)&sW2[q * 4] = *(const float4*)&g_W2p[q * 4];
    }
    __syncthreads();

    float acc[8][4];
#pragma unroll
    for (int j = 0; j < 8; j++)
#pragma unroll
        for (int q = 0; q < 4; q++) acc[j][q] = 0.f;

#pragma unroll
    for (int h = 0; h < 2; h++) {
#pragma unroll
        for (int it = 0; it < 4; ++it) {
            const int idx = it * 256 + tid;
            const int e = idx >> 3, qp = idx & 7;
            const int k = h * 32 + qp * 4;
            const float4 a = __ldg((const float4*)(g_P + (size_t)sSrc[e] * 128 + k));
            const float4 b = __ldg((const float4*)(g_P + (size_t)sDst[e] * 128 + 64 + k));
            const float4 wv = *(const float4*)&sW1r[k];
            const float4 bv = *(const float4*)&sB1[k];
            const float d2 = sD2[e];
            float* dst = &sM[e * 36 + (qp >> 1) * 8 + (qp & 1)];
            dst[0] = silu_f(a.x + b.x + d2 * wv.x + bv.x);
            dst[2] = silu_f(a.y + b.y + d2 * wv.y + bv.y);
            dst[4] = silu_f(a.z + b.z + d2 * wv.z + bv.z);
            dst[6] = silu_f(a.w + b.w + d2 * wv.w + bv.w);
        }
        __syncthreads();

#pragma unroll
        for (int ksl = 0; ksl < 4; ksl++) {
            const int ks = h * 4 + ksl;
            uint32_t af[4], bf[2];
            const int r = warp * 16 + gq;
            const uint2 lo = *(const uint2*)&sMu[r * 36 + ksl * 8 + 2 * tq];
            const uint2 hi = *(const uint2*)&sMu[(r + 8) * 36 + ksl * 8 + 2 * tq];
            af[0] = lo.x; af[1] = hi.x; af[2] = lo.y; af[3] = hi.y;
#pragma unroll
            for (int j = 0; j < 8; j++) {
                const int c = j * 8 + gq;
                const uint2 b = *(const uint2*)&sW2u[c * 72 + ks * 8 + 2 * tq];
                bf[0] = b.x; bf[1] = b.y;
                mma_tf32(acc[j], af, bf);
            }
        }
        if (h == 0) __syncthreads();
    }

    const int r0 = warp * 16 + gq;
    const int n0 = sSrc[r0], n1 = sSrc[r0 + 8];
    float part0 = 0.f, part1 = 0.f;
#pragma unroll
    for (int j = 0; j < 8; j++) {
        const int c = j * 8 + tq * 2;
        const float bb0 = sB2[c], bb1 = sB2[c + 1];
        const float px0 = sPx[c], px1 = sPx[c + 1];
        const float v0 = silu_f(acc[j][0] + bb0);
        const float v1 = silu_f(acc[j][1] + bb1);
        const float v2 = silu_f(acc[j][2] + bb0);
        const float v3 = silu_f(acc[j][3] + bb1);
        part0 += v0 * px0 + v1 * px1;
        part1 += v2 * px0 + v3 * px1;
        red_add_v2(g_dh + (size_t)n0 * 64 + c, v0, v1);
        red_add_v2(g_dh + (size_t)n1 * 64 + c, v2, v3);
    }
    part0 += __shfl_xor_sync(0xffffffffu, part0, 1);
    part0 += __shfl_xor_sync(0xffffffffu, part0, 2);
    part1 += __shfl_xor_sync(0xffffffffu, part1, 1);
    part1 += __shfl_xor_sync(0xffffffffu, part1, 2);
    if (tq == 0) {
        atomicAdd(&g_dx[(size_t)n0 * 3 + 0], part0 * sDirx[r0]);
        atomicAdd(&g_dx[(size_t)n0 * 3 + 1], part0 * sDiry[r0]);
        atomicAdd(&g_dx[(size_t)n0 * 3 + 2], part0 * sDirz[r0]);
        atomicAdd(&g_dx[(size_t)n1 * 3 + 0], part1 * sDirx[r0 + 8]);
        atomicAdd(&g_dx[(size_t)n1 * 3 + 1], part1 * sDiry[r0 + 8]);
        atomicAdd(&g_dx[(size_t)n1 * 3 + 2], part1 * sDirz[r0 + 8]);
    }
}

// ---------------- launch ----------------
extern "C" void kernel_launch(void* const* d_in, const int* in_sizes, int n_in,
                              void* d_out, int out_size) {
    const float* x   = (const float*)d_in[0];
    const float* h   = (const float*)d_in[1];
    const int*   ei  = (const int*)d_in[2];
    const float* pw1 = (const float*)d_in[3];
    const float* pb1 = (const float*)d_in[4];
    const float* pw2 = (const float*)d_in[5];
    const float* pb2 = (const float*)d_in[6];
    const float* pxw = (const float*)d_in[7];
    const float* hw1 = (const float*)d_in[8];
    const float* hb1 = (const float*)d_in[9];
    const float* hw2 = (const float*)d_in[10];
    const float* hb2 = (const float*)d_in[11];

    float* out   = (float*)d_out;
    float* out_x = out;
    float* out_h = out + (size_t)BN * 3;

    const int GSMEM = 2 * 10240 * (int)sizeof(float);                  // 81920 B
    const int FSMEM = (10240 + 128 * 136) * (int)sizeof(float);        // 110592 B
    const int EDGE_SMEM = (64 * 72 + EPB * 36) * (int)sizeof(float);   // 36864 B
    cudaFuncSetAttribute(gemm_p, cudaFuncAttributeMaxDynamicSharedMemorySize, GSMEM);
    cudaFuncSetAttribute(gemm_fused, cudaFuncAttributeMaxDynamicSharedMemorySize, FSMEM);
    cudaFuncSetAttribute(edge_kernel, cudaFuncAttributeMaxDynamicSharedMemorySize, EDGE_SMEM);

    prep_kernel<<<64, 256>>>(pw1, hw1, hw2, pw2);                        // weights only
    gemm_p<<<512 + 256, 256, GSMEM>>>(h);                                // P + zeroing tail
    edge_kernel<<<NE / EPB, 256, EDGE_SMEM>>>(x, ei, pw1, pb1, pb2, pxw);
    gemm_fused<<<BN / 128 + 256, 256, FSMEM>>>(h, hb1, hb2, out_h, x, out_x);
}

// round 11
// speedup vs baseline: 1.4876x; 1.2566x over previous
#include <cuda_runtime.h>
#include <math.h>
#include <stdint.h>

#define BN   65536
#define NPB  16384
#define NE   262144
#define EPB  128

// g_Bp: 14 K32-chunks x 128 n x 24 words (bf16x2 pairs, pair-slot interleaved)
__device__ __align__(16) float g_P [(size_t)BN * 128];
__device__ __align__(16) float g_dh[(size_t)BN * 64];
__device__ __align__(16) float g_dx[(size_t)BN * 3];
__device__ __align__(16) float g_Bp[14 * 128 * 24];
__device__ __align__(16) float g_W2p[64 * 40];

__device__ __forceinline__ float silu_f(float v) {
    return v * (1.0f / (1.0f + __expf(-v)));
}
__device__ __forceinline__ uint32_t pack_bf16(float lo, float hi) {
    uint32_t r;
    asm("cvt.rn.bf16x2.f32 %0, %1, %2;" : "=r"(r) : "f"(hi), "f"(lo));
    return r;
}
__device__ __forceinline__ void mma_bf16(float* c, const uint32_t* a, const uint32_t* b) {
    asm volatile("mma.sync.aligned.m16n8k16.row.col.f32.bf16.bf16.f32 "
        "{%0,%1,%2,%3}, {%4,%5,%6,%7}, {%8,%9}, {%0,%1,%2,%3};"
        : "+f"(c[0]), "+f"(c[1]), "+f"(c[2]), "+f"(c[3])
        : "r"(a[0]), "r"(a[1]), "r"(a[2]), "r"(a[3]), "r"(b[0]), "r"(b[1]));
}
__device__ __forceinline__ void red_add_v2(float* p, float a, float b) {
    asm volatile("red.global.add.v2.f32 [%0], {%1,%2};"
                 :: "l"(p), "f"(a), "f"(b) : "memory");
}
__device__ __forceinline__ void cp_async16(uint32_t dst, const void* src) {
    asm volatile("cp.async.cg.shared.global [%0], [%1], 16;" :: "r"(dst), "l"(src));
}

// ---------------- prep: weights -> bf16x2 pair-interleaved ------------------
__global__ void prep_kernel(const float* __restrict__ pw1,
                            const float* __restrict__ hw1,
                            const float* __restrict__ hw2,
                            const float* __restrict__ pw2)
{
    const int stride = gridDim.x * blockDim.x;
    const int idx0 = blockIdx.x * blockDim.x + threadIdx.x;
    // g_Bp: word w<16: group g=w>>3, slot s=w&7 -> pair p=(s>>1)+((s&1)<<2),
    // k_local = 16g+2p
    for (int i = idx0; i < 14 * 128 * 24; i += stride) {
        const int w = i % 24, n = (i / 24) & 127, c = i / (24 * 128);
        float v = 0.f;
        if (w < 16) {
            const int g = w >> 3, s = w & 7;
            const int p = (s >> 1) + ((s & 1) << 2);
            const int kl = 16 * g + 2 * p;
            float lo, hi;
            if (c < 4) {
                const int k = c * 32 + kl;
                if (n < 64) { lo = pw1[k * 64 + n];         hi = pw1[(k + 1) * 64 + n]; }
                else        { lo = pw1[(128 + k) * 64 + (n - 64)];
                              hi = pw1[(129 + k) * 64 + (n - 64)]; }
            } else if (c < 10) {
                const int k = (c - 4) * 32 + kl;
                lo = hw1[k * 128 + n]; hi = hw1[(k + 1) * 128 + n];
            } else {
                const int k = (c - 10) * 32 + kl;
                lo = hw2[k * 128 + n]; hi = hw2[(k + 1) * 128 + n];
            }
            v = __uint_as_float(pack_bf16(lo, hi));
        }
        g_Bp[i] = v;
    }
    // g_W2p: [n][40], w<32: g=w>>3 (4 groups), k = 16g+2p
    for (int i = idx0; i < 64 * 40; i += stride) {
        const int w = i % 40, n = i / 40;
        float v = 0.f;
        if (w < 32) {
            const int g = w >> 3, s = w & 7;
            const int p = (s >> 1) + ((s & 1) << 2);
            const int k = 16 * g + 2 * p;
            v = __uint_as_float(pack_bf16(pw2[k * 64 + n], pw2[(k + 1) * 64 + n]));
        }
        g_W2p[i] = v;
    }
}

// ============ gemm_p: bf16 CTA 128x128, warp 32x64 + zero tail ==============
// buffers p: A @ p*6144, B @ p*6144+3072 (words); chunk = K32 = 2 k16-groups
__global__ __launch_bounds__(256, 2) void gemm_p(const float* __restrict__ A)
{
    extern __shared__ float sm[];
    const int BUFW = 6144;

    if (blockIdx.x >= 512) {          // zero g_dh / g_dx (overlaps P compute)
        const int t0 = (blockIdx.x - 512) * 256 + threadIdx.x;
        float4 z = make_float4(0.f, 0.f, 0.f, 0.f);
        const int n1 = BN * 16;
        const int n2 = BN * 3 / 4;
        for (int i = t0; i < n1 + n2; i += 256 * 256) {
            if (i < n1) ((float4*)g_dh)[i] = z;
            else        ((float4*)g_dx)[i - n1] = z;
        }
        return;
    }

    const int tid  = threadIdx.x;
    const int lane = tid & 31, warp = tid >> 5;
    const int wm = warp & 3, wn = warp >> 2;
    const int gq = lane >> 2, tq = lane & 3;
    const int m0 = blockIdx.x * 128;
    const uint32_t smem_u32 = (uint32_t)__cvta_generic_to_shared(sm);

    float acc[2][8][4];
#pragma unroll
    for (int i = 0; i < 2; i++)
#pragma unroll
        for (int j = 0; j < 8; j++)
#pragma unroll
            for (int q = 0; q < 4; q++) acc[i][j][q] = 0.f;

    float4 ra[4];
    const int am = tid >> 1;           // row
    const int ag = tid & 1;            // k16-group within chunk

    auto ldgA = [&](int k0) {
        const float* src = A + (size_t)(m0 + am) * 128 + k0 + ag * 16;
        ra[0] = *(const float4*)(src);
        ra[1] = *(const float4*)(src + 4);
        ra[2] = *(const float4*)(src + 8);
        ra[3] = *(const float4*)(src + 12);
    };
    // slots for float4 #q: s0 = slot(2q), s1 = slot(2q+1):
    // q0 -> 0,2 ; q1 -> 4,6 ; q2 -> 1,3 ; q3 -> 5,7
    auto stsA = [&](int p) {
        uint32_t w[8];
        w[0] = pack_bf16(ra[0].x, ra[0].y); w[2] = pack_bf16(ra[0].z, ra[0].w);
        w[4] = pack_bf16(ra[1].x, ra[1].y); w[6] = pack_bf16(ra[1].z, ra[1].w);
        w[1] = pack_bf16(ra[2].x, ra[2].y); w[3] = pack_bf16(ra[2].z, ra[2].w);
        w[5] = pack_bf16(ra[3].x, ra[3].y); w[7] = pack_bf16(ra[3].z, ra[3].w);
        uint32_t* bA = (uint32_t*)(sm + p * BUFW);
        *(uint4*)&bA[am * 24 + ag * 8]     = make_uint4(w[0], w[1], w[2], w[3]);
        *(uint4*)&bA[am * 24 + ag * 8 + 4] = make_uint4(w[4], w[5], w[6], w[7]);
    };
    auto cpB = [&](int chunk, int p) {
        const float* src = g_Bp + (size_t)chunk * 3072;
        const uint32_t dst = smem_u32 + (p * BUFW + 3072) * 4;
#pragma unroll
        for (int it = 0; it < 3; it++) {
            const int q = tid + it * 256;
            cp_async16(dst + q * 16, src + q * 4);
        }
        asm volatile("cp.async.commit_group;" ::: "memory");
    };
    auto compute = [&](int p) {
        const uint32_t* bA = (const uint32_t*)(sm + p * BUFW);
        const uint32_t* bB = (const uint32_t*)(sm + p * BUFW + 3072);
#pragma unroll
        for (int g = 0; g < 2; g++) {
            uint32_t af[2][4], bf[8][2];
#pragma unroll
            for (int i = 0; i < 2; i++) {
                const int r = wm * 32 + i * 16 + gq;
                const uint2 lo = *(const uint2*)&bA[r * 24 + g * 8 + 2 * tq];
                const uint2 hi = *(const uint2*)&bA[(r + 8) * 24 + g * 8 + 2 * tq];
                af[i][0] = lo.x; af[i][1] = hi.x; af[i][2] = lo.y; af[i][3] = hi.y;
            }
#pragma unroll
            for (int j = 0; j < 8; j++) {
                const int c = wn * 64 + j * 8 + gq;
                const uint2 b = *(const uint2*)&bB[c * 24 + g * 8 + 2 * tq];
                bf[j][0] = b.x; bf[j][1] = b.y;
            }
#pragma unroll
            for (int i = 0; i < 2; i++)
#pragma unroll
                for (int j = 0; j < 8; j++)
                    mma_bf16(acc[i][j], af[i], bf[j]);
        }
    };

    ldgA(0); cpB(0, 0); stsA(0);
    asm volatile("cp.async.wait_group 0;" ::: "memory");
    __syncthreads();
    for (int c = 0; c < 4; c++) {
        if (c + 1 < 4) { ldgA((c + 1) * 32); cpB(c + 1, (c + 1) & 1); }
        compute(c & 1);
        if (c + 1 < 4) {
            stsA((c + 1) & 1);
            asm volatile("cp.async.wait_group 0;" ::: "memory");
            __syncthreads();
        }
    }

#pragma unroll
    for (int i = 0; i < 2; i++)
#pragma unroll
        for (int h2 = 0; h2 < 2; h2++) {
            const int r = m0 + wm * 32 + i * 16 + gq + h2 * 8;
#pragma unroll
            for (int j = 0; j < 8; j++) {
                const int c = wn * 64 + j * 8 + tq * 2;
                *(float2*)(g_P + (size_t)r * 128 + c) =
                    make_float2(acc[i][j][h2 * 2 + 0], acc[i][j][h2 * 2 + 1]);
            }
        }
}

// ===== fused node MLP (bf16), 2 CTAs/SM ======================================
// words: B0 @0, B1 @3072, A_p @6144+p*3072, tT @6144 [128][72] (overlays A)
__global__ __launch_bounds__(256, 2) void gemm_fused(
    const float* __restrict__ A,
    const float* __restrict__ b1,
    const float* __restrict__ b2,
    float* __restrict__ OutH,
    const float* __restrict__ X,
    float* __restrict__ OutX)
{
    extern __shared__ float sm[];
    __shared__ float sB1s[128], sB2s[128];

    if (blockIdx.x >= 512) {
        const int t0 = (blockIdx.x - 512) * 256 + threadIdx.x;
        for (int i = t0; i < BN * 3; i += 256 * 256)
            OutX[i] = X[i] + g_dx[i];
        return;
    }

    const int tid  = threadIdx.x;
    const int lane = tid & 31, warp = tid >> 5;
    const int wm = warp & 3, wn = warp >> 2;
    const int gq = lane >> 2, tq = lane & 3;
    const int m0 = blockIdx.x * 128;
    const uint32_t smem_u32 = (uint32_t)__cvta_generic_to_shared(sm);
    uint32_t* tT = (uint32_t*)(sm + 6144);

    if (tid < 128) sB1s[tid] = b1[tid];
    else           sB2s[tid - 128] = b2[tid - 128];

    float4 ra[4];
    const int am = tid >> 1;
    const int ag = tid & 1;

    auto ldgA = [&](int k0) {
        const int f = k0 + ag * 16;
        const float* src = (f < 128) ? (A + (size_t)(m0 + am) * 128 + f)
                                     : (g_dh + (size_t)(m0 + am) * 64 + (f - 128));
        ra[0] = *(const float4*)(src);
        ra[1] = *(const float4*)(src + 4);
        ra[2] = *(const float4*)(src + 8);
        ra[3] = *(const float4*)(src + 12);
    };
    auto stsA = [&](int p) {
        uint32_t w[8];
        w[0] = pack_bf16(ra[0].x, ra[0].y); w[2] = pack_bf16(ra[0].z, ra[0].w);
        w[4] = pack_bf16(ra[1].x, ra[1].y); w[6] = pack_bf16(ra[1].z, ra[1].w);
        w[1] = pack_bf16(ra[2].x, ra[2].y); w[3] = pack_bf16(ra[2].z, ra[2].w);
        w[5] = pack_bf16(ra[3].x, ra[3].y); w[7] = pack_bf16(ra[3].z, ra[3].w);
        uint32_t* bA = (uint32_t*)(sm + 6144 + p * 3072);
        *(uint4*)&bA[am * 24 + ag * 8]     = make_uint4(w[0], w[1], w[2], w[3]);
        *(uint4*)&bA[am * 24 + ag * 8 + 4] = make_uint4(w[4], w[5], w[6], w[7]);
    };
    auto cpB = [&](int chunk, int p) {
        const float* src = g_Bp + (size_t)chunk * 3072;
        const uint32_t dst = smem_u32 + (p * 3072) * 4;
#pragma unroll
        for (int it = 0; it < 3; it++) {
            const int q = tid + it * 256;
            cp_async16(dst + q * 16, src + q * 4);
        }
        asm volatile("cp.async.commit_group;" ::: "memory");
    };

    // ---------------- phase 1: t = silu([h|dh]@W1 + b1) ----------------
    {
        float acc[2][8][4];
#pragma unroll
        for (int i = 0; i < 2; i++)
#pragma unroll
            for (int j = 0; j < 8; j++)
#pragma unroll
                for (int q = 0; q < 4; q++) acc[i][j][q] = 0.f;

        auto compute = [&](int p) {
            const uint32_t* bA = (const uint32_t*)(sm + 6144 + p * 3072);
            const uint32_t* bB = (const uint32_t*)(sm + p * 3072);
#pragma unroll
            for (int g = 0; g < 2; g++) {
                uint32_t af[2][4], bf[8][2];
#pragma unroll
                for (int i = 0; i < 2; i++) {
                    const int r = wm * 32 + i * 16 + gq;
                    const uint2 lo = *(const uint2*)&bA[r * 24 + g * 8 + 2 * tq];
                    const uint2 hi = *(const uint2*)&bA[(r + 8) * 24 + g * 8 + 2 * tq];
                    af[i][0] = lo.x; af[i][1] = hi.x; af[i][2] = lo.y; af[i][3] = hi.y;
                }
#pragma unroll
                for (int j = 0; j < 8; j++) {
                    const int c = wn * 64 + j * 8 + gq;
                    const uint2 b = *(const uint2*)&bB[c * 24 + g * 8 + 2 * tq];
                    bf[j][0] = b.x; bf[j][1] = b.y;
                }
#pragma unroll
                for (int i = 0; i < 2; i++)
#pragma unroll
                    for (int j = 0; j < 8; j++)
                        mma_bf16(acc[i][j], af[i], bf[j]);
            }
        };

        ldgA(0); cpB(4, 0); stsA(0);
        asm volatile("cp.async.wait_group 0;" ::: "memory");
        __syncthreads();
        for (int c = 0; c < 6; c++) {
            if (c + 1 < 6) { ldgA((c + 1) * 32); cpB(5 + c, (c + 1) & 1); }
            if (c == 5)    cpB(10, 0);   // prefetch phase-2 chunk into dead buf0
            compute(c & 1);
            if (c + 1 < 6) {
                stsA((c + 1) & 1);
                asm volatile("cp.async.wait_group 0;" ::: "memory");
                __syncthreads();
            } else {
                __syncthreads();
            }
        }

        // epilogue 1: silu(+b1) -> tT bf16x2; word @ rl*72 + g*8 + slot,
        // g = wn*4 + (j>>1), slot = tq*2 + (j&1)
#pragma unroll
        for (int i = 0; i < 2; i++)
#pragma unroll
            for (int h2 = 0; h2 < 2; h2++) {
                const int rl = wm * 32 + i * 16 + gq + h2 * 8;
#pragma unroll
                for (int j = 0; j < 8; j++) {
                    const int c = wn * 64 + j * 8 + tq * 2;
                    const float v0 = silu_f(acc[i][j][h2 * 2 + 0] + sB1s[c]);
                    const float v1 = silu_f(acc[i][j][h2 * 2 + 1] + sB1s[c + 1]);
                    tT[rl * 72 + (wn * 4 + (j >> 1)) * 8 + tq * 2 + (j & 1)] =
                        pack_bf16(v0, v1);
                }
            }
    }

    // ---------------- phase 2: out = h + t@W2 + b2 ----------------
    {
        float acc[2][8][4];
#pragma unroll
        for (int i = 0; i < 2; i++)
#pragma unroll
            for (int j = 0; j < 8; j++)
#pragma unroll
                for (int q = 0; q < 4; q++) acc[i][j][q] = 0.f;

        cpB(11, 1);
        asm volatile("cp.async.wait_group 1;" ::: "memory");  // chunk 10 ready
        __syncthreads();                                       // + tT visible

        for (int kc = 0; kc < 4; kc++) {
            const uint32_t* bB = (const uint32_t*)(sm + (kc & 1) * 3072);
#pragma unroll
            for (int ks = 0; ks < 2; ks++) {
                const int kg = kc * 2 + ks;       // k16-group over K=128
                uint32_t af[2][4], bf[8][2];
#pragma unroll
                for (int i = 0; i < 2; i++) {
                    const int r = wm * 32 + i * 16 + gq;
                    const uint2 lo = *(const uint2*)&tT[r * 72 + kg * 8 + 2 * tq];
                    const uint2 hi = *(const uint2*)&tT[(r + 8) * 72 + kg * 8 + 2 * tq];
                    af[i][0] = lo.x; af[i][1] = hi.x; af[i][2] = lo.y; af[i][3] = hi.y;
                }
#pragma unroll
                for (int j = 0; j < 8; j++) {
                    const int c = wn * 64 + j * 8 + gq;
                    const uint2 b = *(const uint2*)&bB[c * 24 + ks * 8 + 2 * tq];
                    bf[j][0] = b.x; bf[j][1] = b.y;
                }
#pragma unroll
                for (int i = 0; i < 2; i++)
#pragma unroll
                    for (int j = 0; j < 8; j++)
                        mma_bf16(acc[i][j], af[i], bf[j]);
            }
            if (kc < 3) {
                asm volatile("cp.async.wait_group 0;" ::: "memory");
                __syncthreads();
                if (kc + 2 < 4) cpB(12 + kc, kc & 1);
            }
        }

#pragma unroll
        for (int i = 0; i < 2; i++)
#pragma unroll
            for (int h2 = 0; h2 < 2; h2++) {
                const int r = m0 + wm * 32 + i * 16 + gq + h2 * 8;
#pragma unroll
                for (int j = 0; j < 8; j++) {
                    const int c = wn * 64 + j * 8 + tq * 2;
                    const size_t base = (size_t)r * 128 + c;
                    const float2 hh = *(const float2*)(A + base);
                    const float v0 = acc[i][j][h2 * 2 + 0] + sB2s[c] + hh.x;
                    const float v1 = acc[i][j][h2 * 2 + 1] + sB2s[c + 1] + hh.y;
                    *(float2*)(OutH + base) = make_float2(v0, v1);
                }
            }
    }
}

// -------- edge kernel (bf16): 128 edges/block, 256 threads, 4 CTAs/SM -------
__global__ __launch_bounds__(256, 4) void edge_kernel(
    const float* __restrict__ x,
    const int*   __restrict__ edges,
    const float* __restrict__ W1,
    const float* __restrict__ b1,
    const float* __restrict__ b2,
    const float* __restrict__ pxw)
{
    extern __shared__ float dyn[];
    uint32_t* sW2 = (uint32_t*)dyn;            // [64 n][40]
    uint32_t* sM  = (uint32_t*)(dyn + 2560);   // [128 e][40]

    __shared__ int   sSrc[EPB], sDst[EPB];
    __shared__ float sD2[EPB];
    __shared__ float sDirx[EPB], sDiry[EPB], sDirz[EPB];
    __shared__ float sB1[64], sB2[64], sPx[64], sW1r[64];

    const int tid  = threadIdx.x;
    const int lane = tid & 31, warp = tid >> 5;
    const int gq = lane >> 2, tq = lane & 3;
    const int e0 = blockIdx.x * EPB;

    if (tid < EPB) {
        const int eg = e0 + tid;
        const int b  = eg >> 16;
        const int2 sd = ((const int2*)edges)[eg];
        const int gi = b * NPB + sd.x;
        const int gj = b * NPB + sd.y;
        sSrc[tid] = gi; sDst[tid] = gj;
        const float xi0 = x[(size_t)gi * 3 + 0], xi1 = x[(size_t)gi * 3 + 1], xi2 = x[(size_t)gi * 3 + 2];
        const float xj0 = x[(size_t)gj * 3 + 0], xj1 = x[(size_t)gj * 3 + 1], xj2 = x[(size_t)gj * 3 + 2];
        const float d0 = xi0 - xj0, d1 = xi1 - xj1, d2c = xi2 - xj2;
        float d2 = d0 * d0 + d1 * d1 + d2c * d2c;
        d2 = fmaxf(d2, 1e-12f);
        sD2[tid] = d2;
        const float inv = 1.0f / (sqrtf(d2) + 1e-8f);
        sDirx[tid] = d0 * inv; sDiry[tid] = d1 * inv; sDirz[tid] = d2c * inv;
    }
    if (tid >= 128 && tid < 192) {
        const int t = tid - 128;
        sB1[t] = b1[t];
        sB2[t] = b2[t];
        sPx[t] = pxw[t];
        sW1r[t] = W1[256 * 64 + t];
    }
    // W2 prepped: 2560 words = 640 uint4
#pragma unroll
    for (int it = 0; it < 3; it++) {
        const int q = tid + it * 256;
        if (q < 640) *(uint4*)&sW2[q * 4] = *(const uint4*)&g_W2p[q * 4];
    }
    __syncthreads();

    // gather + silu -> sM bf16x2 (single pass over K=64)
    // item = (edge e, quad q of 16); k=4q; g=q>>2; qm=q&3;
    // s0 = (qm&1)*4 + (qm>>1), s1 = s0+2
#pragma unroll
    for (int it = 0; it < 8; ++it) {
        const int idx = it * 256 + tid;
        const int e = idx >> 4, q = idx & 15;
        const int k = q * 4;
        const float4 a = __ldg((const float4*)(g_P + (size_t)sSrc[e] * 128 + k));
        const float4 b = __ldg((const float4*)(g_P + (size_t)sDst[e] * 128 + 64 + k));
        const float4 wv = *(const float4*)&sW1r[k];
        const float4 bv = *(const float4*)&sB1[k];
        const float d2 = sD2[e];
        const float v0 = silu_f(a.x + b.x + d2 * wv.x + bv.x);
        const float v1 = silu_f(a.y + b.y + d2 * wv.y + bv.y);
        const float v2 = silu_f(a.z + b.z + d2 * wv.z + bv.z);
        const float v3 = silu_f(a.w + b.w + d2 * wv.w + bv.w);
        const int g = q >> 2, qm = q & 3;
        const int s0 = (qm & 1) * 4 + (qm >> 1);
        uint32_t* dst = &sM[e * 40 + g * 8];
        dst[s0]     = pack_bf16(v0, v1);
        dst[s0 + 2] = pack_bf16(v2, v3);
    }
    __syncthreads();

    // GEMM2: warp = 16 edges x 64 cols, K=64 (4 k16-groups)
    float acc[8][4];
#pragma unroll
    for (int j = 0; j < 8; j++)
#pragma unroll
        for (int q = 0; q < 4; q++) acc[j][q] = 0.f;

#pragma unroll
    for (int g = 0; g < 4; g++) {
        uint32_t af[4], bf[2];
        const int r = warp * 16 + gq;
        const uint2 lo = *(const uint2*)&sM[r * 40 + g * 8 + 2 * tq];
        const uint2 hi = *(const uint2*)&sM[(r + 8) * 40 + g * 8 + 2 * tq];
        af[0] = lo.x; af[1] = hi.x; af[2] = lo.y; af[3] = hi.y;
#pragma unroll
        for (int j = 0; j < 8; j++) {
            const int c = j * 8 + gq;
            const uint2 b = *(const uint2*)&sW2[c * 40 + g * 8 + 2 * tq];
            bf[0] = b.x; bf[1] = b.y;
            mma_bf16(acc[j], af, bf);
        }
    }

    const int r0 = warp * 16 + gq;
    const int n0 = sSrc[r0], n1 = sSrc[r0 + 8];
    float part0 = 0.f, part1 = 0.f;
#pragma unroll
    for (int j = 0; j < 8; j++) {
        const int c = j * 8 + tq * 2;
        const float bb0 = sB2[c], bb1 = sB2[c + 1];
        const float px0 = sPx[c], px1 = sPx[c + 1];
        const float v0 = silu_f(acc[j][0] + bb0);
        const float v1 = silu_f(acc[j][1] + bb1);
        const float v2 = silu_f(acc[j][2] + bb0);
        const float v3 = silu_f(acc[j][3] + bb1);
        part0 += v0 * px0 + v1 * px1;
        part1 += v2 * px0 + v3 * px1;
        red_add_v2(g_dh + (size_t)n0 * 64 + c, v0, v1);
        red_add_v2(g_dh + (size_t)n1 * 64 + c, v2, v3);
    }
    part0 += __shfl_xor_sync(0xffffffffu, part0, 1);
    part0 += __shfl_xor_sync(0xffffffffu, part0, 2);
    part1 += __shfl_xor_sync(0xffffffffu, part1, 1);
    part1 += __shfl_xor_sync(0xffffffffu, part1, 2);
    if (tq == 0) {
        atomicAdd(&g_dx[(size_t)n0 * 3 + 0], part0 * sDirx[r0]);
        atomicAdd(&g_dx[(size_t)n0 * 3 + 1], part0 * sDiry[r0]);
        atomicAdd(&g_dx[(size_t)n0 * 3 + 2], part0 * sDirz[r0]);
        atomicAdd(&g_dx[(size_t)n1 * 3 + 0], part1 * sDirx[r0 + 8]);
        atomicAdd(&g_dx[(size_t)n1 * 3 + 1], part1 * sDiry[r0 + 8]);
        atomicAdd(&g_dx[(size_t)n1 * 3 + 2], part1 * sDirz[r0 + 8]);
    }
}

// ---------------- launch ----------------
extern "C" void kernel_launch(void* const* d_in, const int* in_sizes, int n_in,
                              void* d_out, int out_size) {
    const float* x   = (const float*)d_in[0];
    const float* h   = (const float*)d_in[1];
    const int*   ei  = (const int*)d_in[2];
    const float* pw1 = (const float*)d_in[3];
    const float* pb1 = (const float*)d_in[4];
    const float* pw2 = (const float*)d_in[5];
    const float* pb2 = (const float*)d_in[6];
    const float* pxw = (const float*)d_in[7];
    const float* hw1 = (const float*)d_in[8];
    const float* hb1 = (const float*)d_in[9];
    const float* hw2 = (const float*)d_in[10];
    const float* hb2 = (const float*)d_in[11];

    float* out   = (float*)d_out;
    float* out_x = out;
    float* out_h = out + (size_t)BN * 3;

    const int GSMEM = 2 * 6144 * (int)sizeof(float);                   // 49152 B
    const int FSMEM = (6144 + 128 * 72) * (int)sizeof(float);          // 61440 B
    const int EDGE_SMEM = (2560 + 128 * 40) * (int)sizeof(float);      // 30720 B
    cudaFuncSetAttribute(gemm_p, cudaFuncAttributeMaxDynamicSharedMemorySize, GSMEM);
    cudaFuncSetAttribute(gemm_fused, cudaFuncAttributeMaxDynamicSharedMemorySize, FSMEM);
    cudaFuncSetAttribute(edge_kernel, cudaFuncAttributeMaxDynamicSharedMemorySize, EDGE_SMEM);

    prep_kernel<<<64, 256>>>(pw1, hw1, hw2, pw2);
    gemm_p<<<512 + 256, 256, GSMEM>>>(h);
    edge_kernel<<<NE / EPB, 256, EDGE_SMEM>>>(x, ei, pw1, pb1, pb2, pxw);
    gemm_fused<<<BN / 128 + 256, 256, FSMEM>>>(h, hb1, hb2, out_h, x, out_x);
}

// round 13
// speedup vs baseline: 1.5170x; 1.0198x over previous
#include <cuda_runtime.h>
#include <math.h>
#include <stdint.h>

#define BN   65536
#define NPB  16384
#define NE   262144
#define EPB  128

// g_Bp: 14 K32-chunks x 128 n x 24 words (bf16x2 pairs, pair-slot interleaved)
__device__ __align__(16) float g_P [(size_t)BN * 128];
__device__ __align__(16) float g_dh[(size_t)BN * 64];
__device__ __align__(16) float g_dx[(size_t)BN * 3];
__device__ __align__(16) float g_Bp[14 * 128 * 24];
__device__ __align__(16) float g_W2p[64 * 40];

__device__ __forceinline__ float silu_f(float v) {
    return v * (1.0f / (1.0f + __expf(-v)));
}
__device__ __forceinline__ uint32_t pack_bf16(float lo, float hi) {
    uint32_t r;
    asm("cvt.rn.bf16x2.f32 %0, %1, %2;" : "=r"(r) : "f"(hi), "f"(lo));
    return r;
}
__device__ __forceinline__ void mma_bf16(float* c, const uint32_t* a, const uint32_t* b) {
    asm volatile("mma.sync.aligned.m16n8k16.row.col.f32.bf16.bf16.f32 "
        "{%0,%1,%2,%3}, {%4,%5,%6,%7}, {%8,%9}, {%0,%1,%2,%3};"
        : "+f"(c[0]), "+f"(c[1]), "+f"(c[2]), "+f"(c[3])
        : "r"(a[0]), "r"(a[1]), "r"(a[2]), "r"(a[3]), "r"(b[0]), "r"(b[1]));
}
__device__ __forceinline__ void red_add_v2(float* p, float a, float b) {
    asm volatile("red.global.add.v2.f32 [%0], {%1,%2};"
                 :: "l"(p), "f"(a), "f"(b) : "memory");
}
__device__ __forceinline__ void cp_async16(uint32_t dst, const void* src) {
    asm volatile("cp.async.cg.shared.global [%0], [%1], 16;" :: "r"(dst), "l"(src));
}

// ---------------- prep: weights -> bf16x2 pair-interleaved ------------------
__global__ void prep_kernel(const float* __restrict__ pw1,
                            const float* __restrict__ hw1,
                            const float* __restrict__ hw2,
                            const float* __restrict__ pw2)
{
    const int stride = gridDim.x * blockDim.x;
    const int idx0 = blockIdx.x * blockDim.x + threadIdx.x;
    for (int i = idx0; i < 14 * 128 * 24; i += stride) {
        const int w = i % 24, n = (i / 24) & 127, c = i / (24 * 128);
        float v = 0.f;
        if (w < 16) {
            const int g = w >> 3, s = w & 7;
            const int p = (s >> 1) + ((s & 1) << 2);
            const int kl = 16 * g + 2 * p;
            float lo, hi;
            if (c < 4) {
                const int k = c * 32 + kl;
                if (n < 64) { lo = pw1[k * 64 + n];         hi = pw1[(k + 1) * 64 + n]; }
                else        { lo = pw1[(128 + k) * 64 + (n - 64)];
                              hi = pw1[(129 + k) * 64 + (n - 64)]; }
            } else if (c < 10) {
                const int k = (c - 4) * 32 + kl;
                lo = hw1[k * 128 + n]; hi = hw1[(k + 1) * 128 + n];
            } else {
                const int k = (c - 10) * 32 + kl;
                lo = hw2[k * 128 + n]; hi = hw2[(k + 1) * 128 + n];
            }
            v = __uint_as_float(pack_bf16(lo, hi));
        }
        g_Bp[i] = v;
    }
    for (int i = idx0; i < 64 * 40; i += stride) {
        const int w = i % 40, n = i / 40;
        float v = 0.f;
        if (w < 32) {
            const int g = w >> 3, s = w & 7;
            const int p = (s >> 1) + ((s & 1) << 2);
            const int k = 16 * g + 2 * p;
            v = __uint_as_float(pack_bf16(pw2[k * 64 + n], pw2[(k + 1) * 64 + n]));
        }
        g_W2p[i] = v;
    }
}

// ============ gemm_p: bf16 CTA 128x128, warp 32x64 + zero tail ==============
__global__ __launch_bounds__(256, 2) void gemm_p(const float* __restrict__ A)
{
    extern __shared__ float sm[];
    const int BUFW = 6144;

    if (blockIdx.x >= 512) {          // zero g_dh / g_dx (overlaps P compute)
        const int t0 = (blockIdx.x - 512) * 256 + threadIdx.x;
        float4 z = make_float4(0.f, 0.f, 0.f, 0.f);
        const int n1 = BN * 16;
        const int n2 = BN * 3 / 4;
        for (int i = t0; i < n1 + n2; i += 256 * 256) {
            if (i < n1) ((float4*)g_dh)[i] = z;
            else        ((float4*)g_dx)[i - n1] = z;
        }
        return;
    }

    const int tid  = threadIdx.x;
    const int lane = tid & 31, warp = tid >> 5;
    const int wm = warp & 3, wn = warp >> 2;
    const int gq = lane >> 2, tq = lane & 3;
    const int m0 = blockIdx.x * 128;
    const uint32_t smem_u32 = (uint32_t)__cvta_generic_to_shared(sm);

    float acc[2][8][4];
#pragma unroll
    for (int i = 0; i < 2; i++)
#pragma unroll
        for (int j = 0; j < 8; j++)
#pragma unroll
            for (int q = 0; q < 4; q++) acc[i][j][q] = 0.f;

    float4 ra[4];
    const int am = tid >> 1;
    const int ag = tid & 1;

    auto ldgA = [&](int k0) {
        const float* src = A + (size_t)(m0 + am) * 128 + k0 + ag * 16;
        ra[0] = *(const float4*)(src);
        ra[1] = *(const float4*)(src + 4);
        ra[2] = *(const float4*)(src + 8);
        ra[3] = *(const float4*)(src + 12);
    };
    auto stsA = [&](int p) {
        uint32_t w[8];
        w[0] = pack_bf16(ra[0].x, ra[0].y); w[2] = pack_bf16(ra[0].z, ra[0].w);
        w[4] = pack_bf16(ra[1].x, ra[1].y); w[6] = pack_bf16(ra[1].z, ra[1].w);
        w[1] = pack_bf16(ra[2].x, ra[2].y); w[3] = pack_bf16(ra[2].z, ra[2].w);
        w[5] = pack_bf16(ra[3].x, ra[3].y); w[7] = pack_bf16(ra[3].z, ra[3].w);
        uint32_t* bA = (uint32_t*)(sm + p * BUFW);
        *(uint4*)&bA[am * 24 + ag * 8]     = make_uint4(w[0], w[1], w[2], w[3]);
        *(uint4*)&bA[am * 24 + ag * 8 + 4] = make_uint4(w[4], w[5], w[6], w[7]);
    };
    auto cpB = [&](int chunk, int p) {
        const float* src = g_Bp + (size_t)chunk * 3072;
        const uint32_t dst = smem_u32 + (p * BUFW + 3072) * 4;
#pragma unroll
        for (int it = 0; it < 3; it++) {
            const int q = tid + it * 256;
            cp_async16(dst + q * 16, src + q * 4);
        }
        asm volatile("cp.async.commit_group;" ::: "memory");
    };
    auto compute = [&](int p) {
        const uint32_t* bA = (const uint32_t*)(sm + p * BUFW);
        const uint32_t* bB = (const uint32_t*)(sm + p * BUFW + 3072);
#pragma unroll
        for (int g = 0; g < 2; g++) {
            uint32_t af[2][4], bf[8][2];
#pragma unroll
            for (int i = 0; i < 2; i++) {
                const int r = wm * 32 + i * 16 + gq;
                const uint2 lo = *(const uint2*)&bA[r * 24 + g * 8 + 2 * tq];
                const uint2 hi = *(const uint2*)&bA[(r + 8) * 24 + g * 8 + 2 * tq];
                af[i][0] = lo.x; af[i][1] = hi.x; af[i][2] = lo.y; af[i][3] = hi.y;
            }
#pragma unroll
            for (int j = 0; j < 8; j++) {
                const int c = wn * 64 + j * 8 + gq;
                const uint2 b = *(const uint2*)&bB[c * 24 + g * 8 + 2 * tq];
                bf[j][0] = b.x; bf[j][1] = b.y;
            }
#pragma unroll
            for (int i = 0; i < 2; i++)
#pragma unroll
                for (int j = 0; j < 8; j++)
                    mma_bf16(acc[i][j], af[i], bf[j]);
        }
    };

    ldgA(0); cpB(0, 0); stsA(0);
    asm volatile("cp.async.wait_group 0;" ::: "memory");
    __syncthreads();
    for (int c = 0; c < 4; c++) {
        if (c + 1 < 4) { ldgA((c + 1) * 32); cpB(c + 1, (c + 1) & 1); }
        compute(c & 1);
        if (c + 1 < 4) {
            stsA((c + 1) & 1);
            asm volatile("cp.async.wait_group 0;" ::: "memory");
            __syncthreads();
        }
    }

#pragma unroll
    for (int i = 0; i < 2; i++)
#pragma unroll
        for (int h2 = 0; h2 < 2; h2++) {
            const int r = m0 + wm * 32 + i * 16 + gq + h2 * 8;
#pragma unroll
            for (int j = 0; j < 8; j++) {
                const int c = wn * 64 + j * 8 + tq * 2;
                *(float2*)(g_P + (size_t)r * 128 + c) =
                    make_float2(acc[i][j][h2 * 2 + 0], acc[i][j][h2 * 2 + 1]);
            }
        }
}

// ===== fused node MLP (bf16), 64-row CTA, 3 CTAs/SM ==========================
// words: B0 @0, B1 @3072, A_p @6144+p*1536, tT @6144 [64][72] (overlays A)
__global__ __launch_bounds__(256, 3) void gemm_fused(
    const float* __restrict__ A,
    const float* __restrict__ b1,
    const float* __restrict__ b2,
    float* __restrict__ OutH,
    const float* __restrict__ X,
    float* __restrict__ OutX)
{
    extern __shared__ float sm[];
    __shared__ float sB1s[128], sB2s[128];

    if (blockIdx.x >= 1024) {
        const int t0 = (blockIdx.x - 1024) * 256 + threadIdx.x;
        for (int i = t0; i < BN * 3; i += 256 * 256)
            OutX[i] = X[i] + g_dx[i];
        return;
    }

    const int tid  = threadIdx.x;
    const int lane = tid & 31, warp = tid >> 5;
    const int wm = warp & 3, wn = warp >> 2;      // rows wm*16, cols wn*64
    const int gq = lane >> 2, tq = lane & 3;
    const int m0 = blockIdx.x * 64;
    const uint32_t smem_u32 = (uint32_t)__cvta_generic_to_shared(sm);
    uint32_t* tT = (uint32_t*)(sm + 6144);        // [64][72]

    if (tid < 128) sB1s[tid] = b1[tid];
    else           sB2s[tid - 128] = b2[tid - 128];

    // A fill: item = tid>>1 over (row 64 x group 2); half = tid&1 covers 8 k
    float4 ra[2];
    const int arow = tid >> 2;
    const int ag   = (tid >> 1) & 1;
    const int ah   = tid & 1;

    auto ldgA = [&](int kc0) {
        const int f = kc0 + ag * 16 + ah * 8;
        const float* src = (f < 128) ? (A + (size_t)(m0 + arow) * 128 + f)
                                     : (g_dh + (size_t)(m0 + arow) * 64 + (f - 128));
        ra[0] = *(const float4*)(src);
        ra[1] = *(const float4*)(src + 4);
    };
    auto stsA = [&](int p) {
        uint32_t* bA = (uint32_t*)(sm + 6144 + p * 1536);
        uint32_t* d = &bA[arow * 24 + ag * 8 + ah];
        d[0] = pack_bf16(ra[0].x, ra[0].y);
        d[2] = pack_bf16(ra[0].z, ra[0].w);
        d[4] = pack_bf16(ra[1].x, ra[1].y);
        d[6] = pack_bf16(ra[1].z, ra[1].w);
    };
    auto cpB = [&](int chunk, int p) {
        const float* src = g_Bp + (size_t)chunk * 3072;
        const uint32_t dst = smem_u32 + (p * 3072) * 4;
#pragma unroll
        for (int it = 0; it < 3; it++) {
            const int q = tid + it * 256;
            cp_async16(dst + q * 16, src + q * 4);
        }
        asm volatile("cp.async.commit_group;" ::: "memory");
    };

    // ---------------- phase 1: t = silu([h|dh]@W1 + b1) ----------------
    {
        float acc[8][4];
#pragma unroll
        for (int j = 0; j < 8; j++)
#pragma unroll
            for (int q = 0; q < 4; q++) acc[j][q] = 0.f;

        auto compute = [&](int p) {
            const uint32_t* bA = (const uint32_t*)(sm + 6144 + p * 1536);
            const uint32_t* bB = (const uint32_t*)(sm + p * 3072);
#pragma unroll
            for (int g = 0; g < 2; g++) {
                uint32_t af[4], bf[8][2];
                const int r = wm * 16 + gq;
                const uint2 lo = *(const uint2*)&bA[r * 24 + g * 8 + 2 * tq];
                const uint2 hi = *(const uint2*)&bA[(r + 8) * 24 + g * 8 + 2 * tq];
                af[0] = lo.x; af[1] = hi.x; af[2] = lo.y; af[3] = hi.y;
#pragma unroll
                for (int j = 0; j < 8; j++) {
                    const int c = wn * 64 + j * 8 + gq;
                    const uint2 b = *(const uint2*)&bB[c * 24 + g * 8 + 2 * tq];
                    bf[j][0] = b.x; bf[j][1] = b.y;
                }
#pragma unroll
                for (int j = 0; j < 8; j++)
                    mma_bf16(acc[j], af, bf[j]);
            }
        };

        ldgA(0); cpB(4, 0); stsA(0);
        asm volatile("cp.async.wait_group 0;" ::: "memory");
        __syncthreads();
        for (int c = 0; c < 6; c++) {
            if (c + 1 < 6) { ldgA((c + 1) * 32); cpB(5 + c, (c + 1) & 1); }
            if (c == 5)    cpB(10, 0);   // prefetch phase-2 chunk into dead buf0
            compute(c & 1);
            if (c + 1 < 6) {
                stsA((c + 1) & 1);
                asm volatile("cp.async.wait_group 0;" ::: "memory");
                __syncthreads();
            } else {
                __syncthreads();
            }
        }

        // epilogue 1: silu(+b1) -> tT bf16x2
#pragma unroll
        for (int h2 = 0; h2 < 2; h2++) {
            const int rl = wm * 16 + gq + h2 * 8;
#pragma unroll
            for (int j = 0; j < 8; j++) {
                const int c = wn * 64 + j * 8 + tq * 2;
                const float v0 = silu_f(acc[j][h2 * 2 + 0] + sB1s[c]);
                const float v1 = silu_f(acc[j][h2 * 2 + 1] + sB1s[c + 1]);
                tT[rl * 72 + (wn * 4 + (j >> 1)) * 8 + tq * 2 + (j & 1)] =
                    pack_bf16(v0, v1);
            }
        }
    }

    // ---------------- phase 2: out = h + t@W2 + b2 ----------------
    {
        float acc[8][4];
#pragma unroll
        for (int j = 0; j < 8; j++)
#pragma unroll
            for (int q = 0; q < 4; q++) acc[j][q] = 0.f;

        cpB(11, 1);
        asm volatile("cp.async.wait_group 1;" ::: "memory");  // chunk 10 ready
        __syncthreads();                                       // + tT visible

        for (int kc = 0; kc < 4; kc++) {
            const uint32_t* bB = (const uint32_t*)(sm + (kc & 1) * 3072);
#pragma unroll
            for (int ks = 0; ks < 2; ks++) {
                const int kg = kc * 2 + ks;       // k16-group over K=128
                uint32_t af[4], bf[8][2];
                const int r = wm * 16 + gq;
                const uint2 lo = *(const uint2*)&tT[r * 72 + kg * 8 + 2 * tq];
                const uint2 hi = *(const uint2*)&tT[(r + 8) * 72 + kg * 8 + 2 * tq];
                af[0] = lo.x; af[1] = hi.x; af[2] = lo.y; af[3] = hi.y;
#pragma unroll
                for (int j = 0; j < 8; j++) {
                    const int c = wn * 64 + j * 8 + gq;
                    const uint2 b = *(const uint2*)&bB[c * 24 + ks * 8 + 2 * tq];
                    bf[j][0] = b.x; bf[j][1] = b.y;
                }
#pragma unroll
                for (int j = 0; j < 8; j++)
                    mma_bf16(acc[j], af, bf[j]);
            }
            if (kc < 3) {
                asm volatile("cp.async.wait_group 0;" ::: "memory");
                __syncthreads();
                if (kc + 2 < 4) cpB(12 + kc, kc & 1);
            }
        }

#pragma unroll
        for (int h2 = 0; h2 < 2; h2++) {
            const int r = m0 + wm * 16 + gq + h2 * 8;
#pragma unroll
            for (int j = 0; j < 8; j++) {
                const int c = wn * 64 + j * 8 + tq * 2;
                const size_t base = (size_t)r * 128 + c;
                const float2 hh = *(const float2*)(A + base);
                const float v0 = acc[j][h2 * 2 + 0] + sB2s[c] + hh.x;
                const float v1 = acc[j][h2 * 2 + 1] + sB2s[c + 1] + hh.y;
                *(float2*)(OutH + base) = make_float2(v0, v1);
            }
        }
    }
}

// -------- edge kernel (bf16): 128 edges/block, 256 threads, 4 CTAs/SM -------
__global__ __launch_bounds__(256, 4) void edge_kernel(
    const float* __restrict__ x,
    const int*   __restrict__ edges,
    const float* __restrict__ W1,
    const float* __restrict__ b1,
    const float* __restrict__ b2,
    const float* __restrict__ pxw)
{
    extern __shared__ float dyn[];
    uint32_t* sW2 = (uint32_t*)dyn;            // [64 n][40]
    uint32_t* sM  = (uint32_t*)(dyn + 2560);   // [128 e][40]

    __shared__ int   sSrc[EPB], sDst[EPB];
    __shared__ float sD2[EPB];
    __shared__ float sDirx[EPB], sDiry[EPB], sDirz[EPB];
    __shared__ float sB1[64], sB2[64], sPx[64], sW1r[64];

    const int tid  = threadIdx.x;
    const int lane = tid & 31, warp = tid >> 5;
    const int gq = lane >> 2, tq = lane & 3;
    const int e0 = blockIdx.x * EPB;

    if (tid < EPB) {
        const int eg = e0 + tid;
        const int b  = eg >> 16;
        const int2 sd = ((const int2*)edges)[eg];
        const int gi = b * NPB + sd.x;
        const int gj = b * NPB + sd.y;
        sSrc[tid] = gi; sDst[tid] = gj;
        const float xi0 = x[(size_t)gi * 3 + 0], xi1 = x[(size_t)gi * 3 + 1], xi2 = x[(size_t)gi * 3 + 2];
        const float xj0 = x[(size_t)gj * 3 + 0], xj1 = x[(size_t)gj * 3 + 1], xj2 = x[(size_t)gj * 3 + 2];
        const float d0 = xi0 - xj0, d1 = xi1 - xj1, d2c = xi2 - xj2;
        float d2 = d0 * d0 + d1 * d1 + d2c * d2c;
        d2 = fmaxf(d2, 1e-12f);
        sD2[tid] = d2;
        const float inv = 1.0f / (sqrtf(d2) + 1e-8f);
        sDirx[tid] = d0 * inv; sDiry[tid] = d1 * inv; sDirz[tid] = d2c * inv;
    }
    if (tid >= 128 && tid < 192) {
        const int t = tid - 128;
        sB1[t] = b1[t];
        sB2[t] = b2[t];
        sPx[t] = pxw[t];
        sW1r[t] = W1[256 * 64 + t];
    }
#pragma unroll
    for (int it = 0; it < 3; it++) {
        const int q = tid + it * 256;
        if (q < 640) *(uint4*)&sW2[q * 4] = *(const uint4*)&g_W2p[q * 4];
    }
    __syncthreads();

#pragma unroll
    for (int it = 0; it < 8; ++it) {
        const int idx = it * 256 + tid;
        const int e = idx >> 4, q = idx & 15;
        const int k = q * 4;
        const float4 a = __ldg((const float4*)(g_P + (size_t)sSrc[e] * 128 + k));
        const float4 b = __ldg((const float4*)(g_P + (size_t)sDst[e] * 128 + 64 + k));
        const float4 wv = *(const float4*)&sW1r[k];
        const float4 bv = *(const float4*)&sB1[k];
        const float d2 = sD2[e];
        const float v0 = silu_f(a.x + b.x + d2 * wv.x + bv.x);
        const float v1 = silu_f(a.y + b.y + d2 * wv.y + bv.y);
        const float v2 = silu_f(a.z + b.z + d2 * wv.z + bv.z);
        const float v3 = silu_f(a.w + b.w + d2 * wv.w + bv.w);
        const int g = q >> 2, qm = q & 3;
        const int s0 = (qm & 1) * 4 + (qm >> 1);
        uint32_t* dst = &sM[e * 40 + g * 8];
        dst[s0]     = pack_bf16(v0, v1);
        dst[s0 + 2] = pack_bf16(v2, v3);
    }
    __syncthreads();

    float acc[8][4];
#pragma unroll
    for (int j = 0; j < 8; j++)
#pragma unroll
        for (int q = 0; q < 4; q++) acc[j][q] = 0.f;

#pragma unroll
    for (int g = 0; g < 4; g++) {
        uint32_t af[4], bf[2];
        const int r = warp * 16 + gq;
        const uint2 lo = *(const uint2*)&sM[r * 40 + g * 8 + 2 * tq];
        const uint2 hi = *(const uint2*)&sM[(r + 8) * 40 + g * 8 + 2 * tq];
        af[0] = lo.x; af[1] = hi.x; af[2] = lo.y; af[3] = hi.y;
#pragma unroll
        for (int j = 0; j < 8; j++) {
            const int c = j * 8 + gq;
            const uint2 b = *(const uint2*)&sW2[c * 40 + g * 8 + 2 * tq];
            bf[0] = b.x; bf[1] = b.y;
            mma_bf16(acc[j], af, bf);
        }
    }

    const int r0 = warp * 16 + gq;
    const int n0 = sSrc[r0], n1 = sSrc[r0 + 8];
    float part0 = 0.f, part1 = 0.f;
#pragma unroll
    for (int j = 0; j < 8; j++) {
        const int c = j * 8 + tq * 2;
        const float bb0 = sB2[c], bb1 = sB2[c + 1];
        const float px0 = sPx[c], px1 = sPx[c + 1];
        const float v0 = silu_f(acc[j][0] + bb0);
        const float v1 = silu_f(acc[j][1] + bb1);
        const float v2 = silu_f(acc[j][2] + bb0);
        const float v3 = silu_f(acc[j][3] + bb1);
        part0 += v0 * px0 + v1 * px1;
        part1 += v2 * px0 + v3 * px1;
        red_add_v2(g_dh + (size_t)n0 * 64 + c, v0, v1);
        red_add_v2(g_dh + (size_t)n1 * 64 + c, v2, v3);
    }
    part0 += __shfl_xor_sync(0xffffffffu, part0, 1);
    part0 += __shfl_xor_sync(0xffffffffu, part0, 2);
    part1 += __shfl_xor_sync(0xffffffffu, part1, 1);
    part1 += __shfl_xor_sync(0xffffffffu, part1, 2);
    if (tq == 0) {
        atomicAdd(&g_dx[(size_t)n0 * 3 + 0], part0 * sDirx[r0]);
        atomicAdd(&g_dx[(size_t)n0 * 3 + 1], part0 * sDiry[r0]);
        atomicAdd(&g_dx[(size_t)n0 * 3 + 2], part0 * sDirz[r0]);
        atomicAdd(&g_dx[(size_t)n1 * 3 + 0], part1 * sDirx[r0 + 8]);
        atomicAdd(&g_dx[(size_t)n1 * 3 + 1], part1 * sDiry[r0 + 8]);
        atomicAdd(&g_dx[(size_t)n1 * 3 + 2], part1 * sDirz[r0 + 8]);
    }
}

// ---------------- launch ----------------
extern "C" void kernel_launch(void* const* d_in, const int* in_sizes, int n_in,
                              void* d_out, int out_size) {
    const float* x   = (const float*)d_in[0];
    const float* h   = (const float*)d_in[1];
    const int*   ei  = (const int*)d_in[2];
    const float* pw1 = (const float*)d_in[3];
    const float* pb1 = (const float*)d_in[4];
    const float* pw2 = (const float*)d_in[5];
    const float* pb2 = (const float*)d_in[6];
    const float* pxw = (const float*)d_in[7];
    const float* hw1 = (const float*)d_in[8];
    const float* hb1 = (const float*)d_in[9];
    const float* hw2 = (const float*)d_in[10];
    const float* hb2 = (const float*)d_in[11];

    float* out   = (float*)d_out;
    float* out_x = out;
    float* out_h = out + (size_t)BN * 3;

    const int GSMEM = 2 * 6144 * (int)sizeof(float);                   // 49152 B
    const int FSMEM = (6144 + 64 * 72) * (int)sizeof(float);           // 43008 B
    const int EDGE_SMEM = (2560 + 128 * 40) * (int)sizeof(float);      // 30720 B
    cudaFuncSetAttribute(gemm_p, cudaFuncAttributeMaxDynamicSharedMemorySize, GSMEM);
    cudaFuncSetAttribute(gemm_fused, cudaFuncAttributeMaxDynamicSharedMemorySize, FSMEM);
    cudaFuncSetAttribute(edge_kernel, cudaFuncAttributeMaxDynamicSharedMemorySize, EDGE_SMEM);

    prep_kernel<<<64, 256>>>(pw1, hw1, hw2, pw2);
    gemm_p<<<512 + 256, 256, GSMEM>>>(h);
    edge_kernel<<<NE / EPB, 256, EDGE_SMEM>>>(x, ei, pw1, pb1, pb2, pxw);
    gemm_fused<<<BN / 64 + 256, 256, FSMEM>>>(h, hb1, hb2, out_h, x, out_x);
}